// round 10
// baseline (speedup 1.0000x reference)
#include <cuda_runtime.h>
#include <cuda_bf16.h>
#include <math.h>
#include <stdint.h>

#define Bz    128
#define Sl    200
#define Dm    128
#define Hh    8
#define HD    16
#define Ll    2
#define DFF   2048
#define HID   512
#define TBLV  1000
#define IDXV  100000
#define TOUTN 8
#define NTOK  (Bz*Sl)   // 25600

// ================= scratch (device globals) =================
__device__ float g_x   [2*NTOK*Dm];
__device__ float g_qkv [2*NTOK*3*Dm];
__device__ __nv_bfloat16 g_hcath[Bz*2*Dm], g_hcatl[Bz*2*Dm];
__device__ __nv_bfloat16 g_hh[Bz*HID],     g_hl[Bz*HID];
__device__ __nv_bfloat16 g_xh [2*NTOK*Dm];
__device__ __nv_bfloat16 g_xl [2*NTOK*Dm];
__device__ __nv_bfloat16 g_ath[2*NTOK*Dm];
__device__ __nv_bfloat16 g_atl[2*NTOK*Dm];
__device__ __nv_bfloat16 g_ffh[(size_t)2*NTOK*DFF];
__device__ __nv_bfloat16 g_ffl[(size_t)2*NTOK*DFF];
__device__ __nv_bfloat16 g_Wqkvh[2*Ll*3*Dm*Dm], g_Wqkvl[2*Ll*3*Dm*Dm];
__device__ __nv_bfloat16 g_Woh  [2*Ll*Dm*Dm],   g_Wol  [2*Ll*Dm*Dm];
__device__ __nv_bfloat16 g_W1h  [2*Ll*DFF*Dm],  g_W1l  [2*Ll*DFF*Dm];
__device__ __nv_bfloat16 g_W2h  [2*Ll*Dm*DFF],  g_W2l  [2*Ll*Dm*DFF];
__device__ __nv_bfloat16 g_Wlinh[HID*2*Dm],     g_Wlinl[HID*2*Dm];

// ================= asm helpers (baseline PTX only) ==========
__device__ __forceinline__ uint32_t smem_u32(const void* p) {
    uint32_t a;
    asm("{ .reg .u64 t; cvta.to.shared.u64 t, %1; cvt.u32.u64 %0, t; }"
        : "=r"(a) : "l"(p));
    return a;
}
__device__ __forceinline__ void ldm_x4(uint32_t* r, uint32_t addr) {
    asm volatile("ldmatrix.sync.aligned.m8n8.x4.shared.b16 {%0,%1,%2,%3}, [%4];"
        : "=r"(r[0]), "=r"(r[1]), "=r"(r[2]), "=r"(r[3]) : "r"(addr));
}
__device__ __forceinline__ void mma16816(float* c, const uint32_t* a,
                                         uint32_t b0, uint32_t b1) {
    asm volatile("mma.sync.aligned.m16n8k16.row.col.f32.bf16.bf16.f32 "
        "{%0,%1,%2,%3}, {%4,%5,%6,%7}, {%8,%9}, {%0,%1,%2,%3};"
        : "+f"(c[0]), "+f"(c[1]), "+f"(c[2]), "+f"(c[3])
        : "r"(a[0]), "r"(a[1]), "r"(a[2]), "r"(a[3]), "r"(b0), "r"(b1));
}
#define CP16(dst, src) \
    asm volatile("cp.async.cg.shared.global [%0], [%1], 16;" :: "r"(dst), "l"(src))
#define CP_COMMIT() asm volatile("cp.async.commit_group;" ::: "memory")
#define CP_WAIT0()  asm volatile("cp.async.wait_group 0;" ::: "memory")

// ================= small utility kernels =================
__global__ void cvt_k(const float* __restrict__ in, __nv_bfloat16* __restrict__ h,
                      __nv_bfloat16* __restrict__ l, int n)
{
    int i = blockIdx.x * 256 + threadIdx.x;
    if (i < n) {
        float v = in[i];
        __nv_bfloat16 hi = __float2bfloat16(v);
        h[i] = hi;
        l[i] = __float2bfloat16(v - __bfloat162float(hi));
    }
}

__global__ void embed2_k(const int* __restrict__ ids0, const int* __restrict__ ids1,
                         const float* __restrict__ t0, const float* __restrict__ t1,
                         float* __restrict__ out,
                         __nv_bfloat16* __restrict__ oh, __nv_bfloat16* __restrict__ ol)
{
    int z = blockIdx.y, n = blockIdx.x, d = threadIdx.x;
    const int*   ids = z ? ids1 : ids0;
    const float* tab = z ? t1   : t0;
    size_t o = ((size_t)z*NTOK + n)*Dm + d;
    float v = tab[(size_t)ids[n]*Dm + d];
    out[o] = v;
    __nv_bfloat16 hi = __float2bfloat16(v);
    oh[o] = hi;
    ol[o] = __float2bfloat16(v - __bfloat162float(hi));
}

// ================= split-bf16 tensor-core GEMM ==============================
// C[M,N] = (Ah+Al)[M,K] @ (Bh+Bl)[N,K]^T + bias   (AlBl dropped)
// Block tile (MI*64)x128, stage BK=32, 8 warps (4x2), warp tile (MI*16)x64.
// 2-stage cp.async ring -> 2 CTAs/SM.
// MI=2: BM=128 (default).  MI=1: BM=64 (better wave balance for N=128 GEMMs).
// CVTB : B raw fp32 [N, ldb] (ldb=K+1); loader converts hi/lo on store (MI=2).
// TOUT==8: time-broadcast epilogue, wlast = Bf[n*ldb + K].
// LNF  : requires N==128. x = LN(x + acc + bias); writes Cf=x, Ch/Cl=x hi/lo.
#define PITCH  80

template<int MI, int TOUT, bool RELU, bool OUTBF16, bool CVTB, bool LNF>
__global__ __launch_bounds__(256, 2)
void gemm_mma(const __nv_bfloat16* __restrict__ Ah, const __nv_bfloat16* __restrict__ Al,
              int lda, size_t sA,
              const __nv_bfloat16* __restrict__ Bh16, const __nv_bfloat16* __restrict__ Bl16,
              const float* __restrict__ Bf,
              int ldb, size_t sB,
              const float* __restrict__ bias, size_t sBias,
              const float* __restrict__ gam, const float* __restrict__ bet,
              float* __restrict__ Cf,
              __nv_bfloat16* __restrict__ Ch, __nv_bfloat16* __restrict__ Cl,
              int ldc, size_t sC, int N, int K)
{
    constexpr int BM     = MI * 64;
    constexpr int TILE_A = BM * PITCH;
    constexpr int TILE_B = 128 * PITCH;
    constexpr int STAGE  = 2*TILE_A + 2*TILE_B;
    extern __shared__ __align__(16) char sm[];

    int tid  = threadIdx.x;
    int wid  = tid >> 5;
    int lane = tid & 31;
    int z = blockIdx.z;
    Ah += (size_t)z * sA;  Al += (size_t)z * sA;
    if (!CVTB) { Bh16 += (size_t)z * sB; Bl16 += (size_t)z * sB; }
    bias += (size_t)z * sBias;
    if (LNF) { gam += (size_t)z * sBias; bet += (size_t)z * sBias; }
    if (LNF)         { Cf += (size_t)z * sC; Ch += (size_t)z * sC; Cl += (size_t)z * sC; }
    else if (OUTBF16){ Ch += (size_t)z * sC; Cl += (size_t)z * sC; }
    else             { Cf += (size_t)z * sC; }

    int m0 = blockIdx.y * BM;
    int n0 = blockIdx.x * 128;

    uint32_t sbase = smem_u32(sm);

    // compute mapping
    int wm = wid & 3;
    int wn = wid >> 2;
    int r8 = lane & 7, quad = lane >> 3;
    int arow = wm*(16*MI) + (quad & 1)*8 + r8;
    int aoff = (quad >> 1)*16;
    int brow = wn*64 + (quad >> 1)*8 + r8;
    int boff = (quad & 1)*16;

    float acc[MI][8][4];
#pragma unroll
    for (int i = 0; i < MI; i++)
#pragma unroll
        for (int j = 0; j < 8; j++)
#pragma unroll
            for (int c = 0; c < 4; c++) acc[i][j][c] = 0.f;

    const int nst = K / 32;

    // B loader mapping (always 128 rows): row tid>>1, 32B at (tid&1)*32
    int brow_l = tid >> 1;
    int bhalf  = tid & 1;
    int sdstB  = brow_l*PITCH + bhalf*32;

    if (!CVTB) {
        const __nv_bfloat16* gBh = Bh16 + (size_t)(n0 + brow_l)*ldb + bhalf*16;
        const __nv_bfloat16* gBl = Bl16 + (size_t)(n0 + brow_l)*ldb + bhalf*16;
        // A loader mapping
        const __nv_bfloat16 *gAh, *gAl;
        int sdstA;
        if (MI == 2) {
            gAh = Ah + (size_t)(m0 + (tid >> 1))*lda + (tid & 1)*16;
            gAl = Al + (size_t)(m0 + (tid >> 1))*lda + (tid & 1)*16;
            sdstA = (tid >> 1)*PITCH + (tid & 1)*32;
        } else {
            gAh = Ah + (size_t)(m0 + (tid >> 2))*lda + (tid & 3)*8;
            gAl = Al + (size_t)(m0 + (tid >> 2))*lda + (tid & 3)*8;
            sdstA = (tid >> 2)*PITCH + (tid & 3)*16;
        }

        auto issue = [&](int s) {
            uint32_t stg = sbase + (s & 1)*STAGE;
            int k0 = s * 32;
            if (MI == 2) {
                CP16(stg + sdstA,               gAh + k0);
                CP16(stg + sdstA + 16,          gAh + k0 + 8);
                CP16(stg + TILE_A + sdstA,      gAl + k0);
                CP16(stg + TILE_A + sdstA + 16, gAl + k0 + 8);
            } else {
                CP16(stg + sdstA,               gAh + k0);
                CP16(stg + TILE_A + sdstA,      gAl + k0);
            }
            CP16(stg + 2*TILE_A + sdstB,               gBh + k0);
            CP16(stg + 2*TILE_A + sdstB + 16,          gBh + k0 + 8);
            CP16(stg + 2*TILE_A + TILE_B + sdstB,      gBl + k0);
            CP16(stg + 2*TILE_A + TILE_B + sdstB + 16, gBl + k0 + 8);
            CP_COMMIT();
        };

        issue(0);

        for (int it = 0; it < nst; ++it) {
            CP_WAIT0();
            __syncthreads();
            if (it + 1 < nst) issue(it + 1);

            uint32_t stb = sbase + (it & 1)*STAGE;
            uint32_t bAh = stb;
            uint32_t bAl = stb + TILE_A;
            uint32_t bBh = stb + 2*TILE_A;
            uint32_t bBl = stb + 2*TILE_A + TILE_B;
#pragma unroll
            for (int ks = 0; ks < 2; ks++) {
                int ko = ks * 32;
                uint32_t ah[MI][4], al[MI][4];
#pragma unroll
                for (int mi = 0; mi < MI; mi++) {
                    ldm_x4(ah[mi], bAh + (arow + mi*16)*PITCH + ko + aoff);
                    ldm_x4(al[mi], bAl + (arow + mi*16)*PITCH + ko + aoff);
                }
#pragma unroll
                for (int pj = 0; pj < 4; pj++) {
                    uint32_t bh4[4], bl4[4];
                    ldm_x4(bh4, bBh + (brow + pj*16)*PITCH + ko + boff);
                    ldm_x4(bl4, bBl + (brow + pj*16)*PITCH + ko + boff);
#pragma unroll
                    for (int mi = 0; mi < MI; mi++) {
                        mma16816(acc[mi][2*pj],   ah[mi], bh4[0], bh4[1]);
                        mma16816(acc[mi][2*pj+1], ah[mi], bh4[2], bh4[3]);
                        mma16816(acc[mi][2*pj],   al[mi], bh4[0], bh4[1]);
                        mma16816(acc[mi][2*pj+1], al[mi], bh4[2], bh4[3]);
                        mma16816(acc[mi][2*pj],   ah[mi], bl4[0], bl4[1]);
                        mma16816(acc[mi][2*pj+1], ah[mi], bl4[2], bl4[3]);
                    }
                }
            }
        }
    } else {
        // 2-stage register path, B fp32 converted on store (MI==2 only)
        int browg = min(n0 + brow_l, N - 1);
        const __nv_bfloat16* gAh = Ah + (size_t)(m0 + (tid >> 1))*lda + (tid & 1)*16;
        const __nv_bfloat16* gAl = Al + (size_t)(m0 + (tid >> 1))*lda + (tid & 1)*16;
        int sdstA = (tid >> 1)*PITCH + (tid & 1)*32;
        const float* gB = Bf + (size_t)browg*ldb + bhalf*16;

        uint4 pa0, pa1, pa2, pa3;
        uint32_t pbh[8], pbl[8];

        auto loadstage = [&](int k0) {
            pa0 = *(const uint4*)(gAh + k0);
            pa1 = *(const uint4*)(gAh + k0 + 8);
            pa2 = *(const uint4*)(gAl + k0);
            pa3 = *(const uint4*)(gAl + k0 + 8);
#pragma unroll
            for (int j = 0; j < 8; j++) {
                float v0 = gB[k0 + 2*j];
                float v1 = gB[k0 + 2*j + 1];
                __nv_bfloat16 h0 = __float2bfloat16(v0);
                __nv_bfloat16 h1 = __float2bfloat16(v1);
                __nv_bfloat162 hp; hp.x = h0; hp.y = h1;
                __nv_bfloat162 lp;
                lp.x = __float2bfloat16(v0 - __bfloat162float(h0));
                lp.y = __float2bfloat16(v1 - __bfloat162float(h1));
                pbh[j] = *(uint32_t*)&hp;
                pbl[j] = *(uint32_t*)&lp;
            }
        };
        auto storestage = [&](int b) {
            char* stg = sm + b*STAGE;
            *(uint4*)(stg + sdstA)                        = pa0;
            *(uint4*)(stg + sdstA + 16)                   = pa1;
            *(uint4*)(stg + TILE_A + sdstA)               = pa2;
            *(uint4*)(stg + TILE_A + sdstA + 16)          = pa3;
            *(uint4*)(stg + 2*TILE_A + sdstB)             = make_uint4(pbh[0],pbh[1],pbh[2],pbh[3]);
            *(uint4*)(stg + 2*TILE_A + sdstB + 16)        = make_uint4(pbh[4],pbh[5],pbh[6],pbh[7]);
            *(uint4*)(stg + 2*TILE_A + TILE_B + sdstB)    = make_uint4(pbl[0],pbl[1],pbl[2],pbl[3]);
            *(uint4*)(stg + 2*TILE_A + TILE_B + sdstB+16) = make_uint4(pbl[4],pbl[5],pbl[6],pbl[7]);
        };

        loadstage(0);
        storestage(0);

        for (int it = 0; it < nst; ++it) {
            int buf = it & 1;
            bool more = (it + 1) < nst;
            if (more) loadstage((it + 1) * 32);
            __syncthreads();

            uint32_t stb = sbase + buf*STAGE;
            uint32_t bAh = stb;
            uint32_t bAl = stb + TILE_A;
            uint32_t bBh = stb + 2*TILE_A;
            uint32_t bBl = stb + 2*TILE_A + TILE_B;
#pragma unroll
            for (int ks = 0; ks < 2; ks++) {
                int ko = ks * 32;
                uint32_t ah[MI][4], al[MI][4];
#pragma unroll
                for (int mi = 0; mi < MI; mi++) {
                    ldm_x4(ah[mi], bAh + (arow + mi*16)*PITCH + ko + aoff);
                    ldm_x4(al[mi], bAl + (arow + mi*16)*PITCH + ko + aoff);
                }
#pragma unroll
                for (int pj = 0; pj < 4; pj++) {
                    uint32_t bh4[4], bl4[4];
                    ldm_x4(bh4, bBh + (brow + pj*16)*PITCH + ko + boff);
                    ldm_x4(bl4, bBl + (brow + pj*16)*PITCH + ko + boff);
#pragma unroll
                    for (int mi = 0; mi < MI; mi++) {
                        mma16816(acc[mi][2*pj],   ah[mi], bh4[0], bh4[1]);
                        mma16816(acc[mi][2*pj+1], ah[mi], bh4[2], bh4[3]);
                        mma16816(acc[mi][2*pj],   al[mi], bh4[0], bh4[1]);
                        mma16816(acc[mi][2*pj+1], al[mi], bh4[2], bh4[3]);
                        mma16816(acc[mi][2*pj],   ah[mi], bl4[0], bl4[1]);
                        mma16816(acc[mi][2*pj+1], ah[mi], bl4[2], bl4[3]);
                    }
                }
            }

            if (more) {
                __syncthreads();
                storestage(buf ^ 1);
            }
        }
    }

    // ---- epilogue ----
    int mrow0 = m0 + wm*(16*MI) + (lane >> 2);
    int ncol0 = n0 + wn*64 + (lane & 3)*2;

    if (LNF) {
        __syncthreads();                 // stage smem reusable
        float* red = (float*)sm;         // [BM rows][8 partials][2]
        int rbase = wm*(16*MI) + (lane >> 2);
        int pcol = wn*4 + (lane & 3);

#pragma unroll
        for (int mi = 0; mi < MI; mi++)
#pragma unroll
        for (int half = 0; half < 2; half++) {
            int row = rbase + mi*16 + half*8;
            int grow = m0 + row;
            float s = 0.f, s2 = 0.f;
#pragma unroll
            for (int nj = 0; nj < 8; nj++) {
                int col = (lane & 3)*2 + wn*64 + nj*8;
                float2 res = *(const float2*)(Cf + (size_t)grow*ldc + col);
                float t0 = acc[mi][nj][2*half]     + bias[col]     + res.x;
                float t1 = acc[mi][nj][2*half + 1] + bias[col + 1] + res.y;
                acc[mi][nj][2*half]     = t0;
                acc[mi][nj][2*half + 1] = t1;
                s  += t0 + t1;
                s2 += t0*t0 + t1*t1;
            }
            red[(row*8 + pcol)*2]     = s;
            red[(row*8 + pcol)*2 + 1] = s2;
        }
        __syncthreads();

#pragma unroll
        for (int mi = 0; mi < MI; mi++)
#pragma unroll
        for (int half = 0; half < 2; half++) {
            int row = rbase + mi*16 + half*8;
            int grow = m0 + row;
            float s = 0.f, s2 = 0.f;
#pragma unroll
            for (int p = 0; p < 8; p++) {
                s  += red[(row*8 + p)*2];
                s2 += red[(row*8 + p)*2 + 1];
            }
            float mean = s * (1.f/128.f);
            float var  = s2 * (1.f/128.f) - mean*mean;
            float inv  = rsqrtf(var + 1e-5f);
#pragma unroll
            for (int nj = 0; nj < 8; nj++) {
                int col = (lane & 3)*2 + wn*64 + nj*8;
                float t0 = acc[mi][nj][2*half];
                float t1 = acc[mi][nj][2*half + 1];
                float y0 = (t0 - mean)*inv*gam[col]     + bet[col];
                float y1 = (t1 - mean)*inv*gam[col + 1] + bet[col + 1];
                float2 yv; yv.x = y0; yv.y = y1;
                *(float2*)(Cf + (size_t)grow*ldc + col) = yv;
                __nv_bfloat16 h0 = __float2bfloat16(y0);
                __nv_bfloat16 h1 = __float2bfloat16(y1);
                __nv_bfloat162 hp; hp.x = h0; hp.y = h1;
                __nv_bfloat162 lp;
                lp.x = __float2bfloat16(y0 - __bfloat162float(h0));
                lp.y = __float2bfloat16(y1 - __bfloat162float(h1));
                *(__nv_bfloat162*)(Ch + (size_t)grow*ldc + col) = hp;
                *(__nv_bfloat162*)(Cl + (size_t)grow*ldc + col) = lp;
            }
        }
        return;
    }

#pragma unroll
    for (int mi = 0; mi < MI; mi++) {
#pragma unroll
        for (int nj = 0; nj < 8; nj++) {
            int col = ncol0 + nj*8;
            if (CVTB && col >= N) continue;
            float b0 = bias[col], b1 = bias[col + 1];
            float w0 = 0.f, w1 = 0.f;
            if (TOUT > 1) {
                w0 = Bf[(size_t)col*ldb + K];
                w1 = Bf[(size_t)(col + 1)*ldb + K];
            }
#pragma unroll
            for (int half = 0; half < 2; half++) {
                int row = mrow0 + mi*16 + half*8;
                float v0 = acc[mi][nj][2*half]     + b0;
                float v1 = acc[mi][nj][2*half + 1] + b1;
                if (RELU) { v0 = fmaxf(v0, 0.f); v1 = fmaxf(v1, 0.f); }
                if (TOUT > 1) {
#pragma unroll
                    for (int tt = 0; tt < TOUTN; tt++) {
                        float2 v; v.x = v0 + tt*w0; v.y = v1 + tt*w1;
                        *(float2*)(Cf + (size_t)(row*TOUTN + tt)*ldc + col) = v;
                    }
                } else if (OUTBF16) {
                    __nv_bfloat16 h0 = __float2bfloat16(v0);
                    __nv_bfloat16 h1 = __float2bfloat16(v1);
                    __nv_bfloat162 hp; hp.x = h0; hp.y = h1;
                    __nv_bfloat162 lp;
                    lp.x = __float2bfloat16(v0 - __bfloat162float(h0));
                    lp.y = __float2bfloat16(v1 - __bfloat162float(h1));
                    *(__nv_bfloat162*)(Ch + (size_t)row*ldc + col) = hp;
                    *(__nv_bfloat162*)(Cl + (size_t)row*ldc + col) = lp;
                } else {
                    float2 v; v.x = v0; v.y = v1;
                    *(float2*)(Cf + (size_t)row*ldc + col) = v;
                }
            }
        }
    }
}

// ================= attention: 2 j-segments per query, merged =================
__global__ __launch_bounds__(512)
void attn_k(const float* __restrict__ qkv,
            __nv_bfloat16* __restrict__ oh, __nv_bfloat16* __restrict__ ol)
{
    int z = blockIdx.y;
    int bh = blockIdx.x;
    int b = bh / Hh, h = bh % Hh;
    __shared__ float ks[Sl][HD];
    __shared__ float vs[Sl][HD];
    __shared__ float ms[Sl], ls[Sl];
    int tid = threadIdx.x;
    const float* base = qkv + ((size_t)z*NTOK + (size_t)b*Sl)*(3*Dm);

    for (int e = tid; e < Sl*HD; e += 512) {
        int s = e / HD, d = e % HD;
        ks[s][d] = base[s*(3*Dm) + Dm   + h*HD + d];
        vs[s][d] = base[s*(3*Dm) + 2*Dm + h*HD + d];
    }
    __syncthreads();

    int seg = (tid < Sl) ? 0 : 1;
    int s   = (tid < Sl) ? tid : tid - Sl;
    bool active = (tid < 2*Sl);

    float m = -1e30f, l = 0.f;
    float acc[HD];
#pragma unroll
    for (int d = 0; d < HD; d++) acc[d] = 0.f;

    if (active) {
        float q[HD];
#pragma unroll
        for (int d = 0; d < HD; d++)
            q[d] = base[s*(3*Dm) + h*HD + d] * 0.25f;   // 1/sqrt(16)

        int j0 = seg * (Sl/2);
        int j1 = j0 + (Sl/2);
        for (int j = j0; j < j1; j++) {
            float sc = 0.f;
#pragma unroll
            for (int d = 0; d < HD; d++) sc = fmaf(q[d], ks[j][d], sc);
            float nm  = fmaxf(m, sc);
            float cor = __expf(m - nm);
            float p   = __expf(sc - nm);
            l = l*cor + p;
#pragma unroll
            for (int d = 0; d < HD; d++) acc[d] = acc[d]*cor + p*vs[j][d];
            m = nm;
        }
    }
    __syncthreads();   // everyone done reading ks/vs

    // seg 1 publishes its state (acc into ks storage, m/l into ms/ls)
    if (active && seg == 1) {
        ms[s] = m; ls[s] = l;
#pragma unroll
        for (int d = 0; d < HD; d++) ks[s][d] = acc[d];
    }
    __syncthreads();

    if (active && seg == 0) {
        float m2 = ms[s], l2 = ls[s];
        float nm = fmaxf(m, m2);
        float c1 = __expf(m - nm);
        float c2 = __expf(m2 - nm);
        float L = l*c1 + l2*c2;
        float inv = 1.f / L;
        size_t o = ((size_t)z*NTOK + (size_t)b*Sl + s)*Dm + h*HD;
#pragma unroll
        for (int d = 0; d < HD; d++) {
            float v = (acc[d]*c1 + ks[s][d]*c2) * inv;
            __nv_bfloat16 hi = __float2bfloat16(v);
            oh[o + d] = hi;
            ol[o + d] = __float2bfloat16(v - __bfloat162float(hi));
        }
    }
}

// ---------------- sequence mean into split hcat --------------------------
__global__ void mean_k(const float* __restrict__ x,
                       __nv_bfloat16* __restrict__ oh, __nv_bfloat16* __restrict__ ol)
{
    int z = blockIdx.y;
    int b = blockIdx.x, d = threadIdx.x;
    const float* xp = x + ((size_t)z*NTOK + (size_t)b*Sl)*Dm;
    float s = 0.f;
    for (int j = 0; j < Sl; j++) s += xp[j*Dm + d];
    float v = s * (1.f/Sl);
    __nv_bfloat16 hi = __float2bfloat16(v);
    oh[b*(2*Dm) + z*Dm + d] = hi;
    ol[b*(2*Dm) + z*Dm + d] = __float2bfloat16(v - __bfloat162float(hi));
}

// ================= launcher =================
extern "C" void kernel_launch(void* const* d_in, const int* in_sizes, int n_in,
                              void* d_out, int out_size)
{
    const int*   tid_seq = (const int*)  d_in[0];
    const int*   iid_seq = (const int*)  d_in[1];
    const float* tab_emb = (const float*)d_in[2];
    const float* idx_emb = (const float*)d_in[3];
    const float* Wqkv = (const float*)d_in[4];
    const float* bqkv = (const float*)d_in[5];
    const float* Wo   = (const float*)d_in[6];
    const float* bo   = (const float*)d_in[7];
    const float* ln1g = (const float*)d_in[8];
    const float* ln1b = (const float*)d_in[9];
    const float* W1   = (const float*)d_in[10];
    const float* b1   = (const float*)d_in[11];
    const float* W2   = (const float*)d_in[12];
    const float* b2   = (const float*)d_in[13];
    const float* ln2g = (const float*)d_in[14];
    const float* ln2b = (const float*)d_in[15];
    const float* Wlin = (const float*)d_in[16];
    const float* blin = (const float*)d_in[17];
    const float* Wtab = (const float*)d_in[18];
    const float* btab = (const float*)d_in[19];
    const float* Widx = (const float*)d_in[20];
    const float* bidx = (const float*)d_in[21];

    float* out     = (float*)d_out;
    float* out_tab = out;
    float* out_idx = out + (size_t)Bz*TOUTN*TBLV;

    float *x, *qkv;
    __nv_bfloat16 *xh, *xl, *ath, *atl, *ffh, *ffl;
    __nv_bfloat16 *hcath, *hcatl, *hh, *hl;
    __nv_bfloat16 *Wqkvh, *Wqkvl, *Woh, *Wol, *W1h, *W1l, *W2h, *W2l;
    __nv_bfloat16 *Wlinh, *Wlinl;
    cudaGetSymbolAddress((void**)&x,    g_x);
    cudaGetSymbolAddress((void**)&qkv,  g_qkv);
    cudaGetSymbolAddress((void**)&xh,   g_xh);
    cudaGetSymbolAddress((void**)&xl,   g_xl);
    cudaGetSymbolAddress((void**)&ath,  g_ath);
    cudaGetSymbolAddress((void**)&atl,  g_atl);
    cudaGetSymbolAddress((void**)&ffh,  g_ffh);
    cudaGetSymbolAddress((void**)&ffl,  g_ffl);
    cudaGetSymbolAddress((void**)&hcath, g_hcath);
    cudaGetSymbolAddress((void**)&hcatl, g_hcatl);
    cudaGetSymbolAddress((void**)&hh,   g_hh);
    cudaGetSymbolAddress((void**)&hl,   g_hl);
    cudaGetSymbolAddress((void**)&Wqkvh, g_Wqkvh);
    cudaGetSymbolAddress((void**)&Wqkvl, g_Wqkvl);
    cudaGetSymbolAddress((void**)&Woh,   g_Woh);
    cudaGetSymbolAddress((void**)&Wol,   g_Wol);
    cudaGetSymbolAddress((void**)&W1h,   g_W1h);
    cudaGetSymbolAddress((void**)&W1l,   g_W1l);
    cudaGetSymbolAddress((void**)&W2h,   g_W2h);
    cudaGetSymbolAddress((void**)&W2l,   g_W2l);
    cudaGetSymbolAddress((void**)&Wlinh, g_Wlinh);
    cudaGetSymbolAddress((void**)&Wlinl, g_Wlinl);

    const int SM128 = 2*(2*128*PITCH + 2*128*PITCH);   // MI=2: 81920
    const int SM64  = 2*(2*64*PITCH  + 2*128*PITCH);   // MI=1: 61440

    cudaFuncSetAttribute(gemm_mma<2,1,false,false,false,false>, cudaFuncAttributeMaxDynamicSharedMemorySize, SM128);
    cudaFuncSetAttribute(gemm_mma<1,1,false,false,false,true >, cudaFuncAttributeMaxDynamicSharedMemorySize, SM64);
    cudaFuncSetAttribute(gemm_mma<2,1,true, true, false,false>, cudaFuncAttributeMaxDynamicSharedMemorySize, SM128);
    cudaFuncSetAttribute(gemm_mma<2,TOUTN,false,false,true,false>, cudaFuncAttributeMaxDynamicSharedMemorySize, SM128);

    const int MT  = NTOK / 128;  // 200
    const int MT2 = NTOK / 64;   // 400
    const size_t sX   = (size_t)NTOK*Dm;
    const size_t sQKV = (size_t)NTOK*3*Dm;
    const size_t sFF  = (size_t)NTOK*DFF;

    cvt_k<<<(2*Ll*3*Dm*Dm + 255)/256, 256>>>(Wqkv, Wqkvh, Wqkvl, 2*Ll*3*Dm*Dm);
    cvt_k<<<(2*Ll*Dm*Dm   + 255)/256, 256>>>(Wo,   Woh,   Wol,   2*Ll*Dm*Dm);
    cvt_k<<<(2*Ll*DFF*Dm  + 255)/256, 256>>>(W1,   W1h,   W1l,   2*Ll*DFF*Dm);
    cvt_k<<<(2*Ll*Dm*DFF  + 255)/256, 256>>>(W2,   W2h,   W2l,   2*Ll*Dm*DFF);

    embed2_k<<<dim3(NTOK, 2), Dm>>>(tid_seq, iid_seq, tab_emb, idx_emb, x, xh, xl);

    for (int l = 0; l < Ll; l++) {
        // qkv = x @ Wqkv^T + b
        gemm_mma<2,1,false,false,false,false><<<dim3(3, MT, 2), 256, SM128>>>(
            xh, xl, Dm, sX,
            Wqkvh + (size_t)l*3*Dm*Dm, Wqkvl + (size_t)l*3*Dm*Dm, nullptr,
            Dm, (size_t)Ll*3*Dm*Dm,
            bqkv + (size_t)l*3*Dm, (size_t)Ll*3*Dm, nullptr, nullptr,
            qkv, nullptr, nullptr, 3*Dm, sQKV, 3*Dm, Dm);

        attn_k<<<dim3(Bz*Hh, 2), 512>>>(qkv, ath, atl);

        // x = LN(x + att @ Wo^T + bo)  -- fused epilogue, BM=64
        gemm_mma<1,1,false,false,false,true><<<dim3(1, MT2, 2), 256, SM64>>>(
            ath, atl, Dm, sX,
            Woh + (size_t)l*Dm*Dm, Wol + (size_t)l*Dm*Dm, nullptr,
            Dm, (size_t)Ll*Dm*Dm,
            bo + (size_t)l*Dm, (size_t)Ll*Dm,
            ln1g + (size_t)l*Dm, ln1b + (size_t)l*Dm,
            x, xh, xl, Dm, sX, Dm, Dm);

        // ff = relu(x @ W1^T + b1) -> bf16 hi/lo
        gemm_mma<2,1,true,true,false,false><<<dim3(DFF/128, MT, 2), 256, SM128>>>(
            xh, xl, Dm, sX,
            W1h + (size_t)l*DFF*Dm, W1l + (size_t)l*DFF*Dm, nullptr,
            Dm, (size_t)Ll*DFF*Dm,
            b1 + (size_t)l*DFF, (size_t)Ll*DFF, nullptr, nullptr,
            nullptr, ffh, ffl, DFF, sFF, DFF, Dm);

        // x = LN(x + ff @ W2^T + b2)  -- fused epilogue, BM=64
        gemm_mma<1,1,false,false,false,true><<<dim3(1, MT2, 2), 256, SM64>>>(
            ffh, ffl, DFF, sFF,
            W2h + (size_t)l*Dm*DFF, W2l + (size_t)l*Dm*DFF, nullptr,
            DFF, (size_t)Ll*Dm*DFF,
            b2 + (size_t)l*Dm, (size_t)Ll*Dm,
            ln2g + (size_t)l*Dm, ln2b + (size_t)l*Dm,
            x, xh, xl, Dm, sX, Dm, DFF);
    }

    mean_k<<<dim3(Bz, 2), Dm>>>(x, hcath, hcatl);

    cvt_k<<<(HID*2*Dm + 255)/256, 256>>>(Wlin, Wlinh, Wlinl, HID*2*Dm);

    // h = relu(hcat @ Wlin^T + blin) -> split   [128,512] K=256
    gemm_mma<2,1,true,true,false,false><<<dim3(HID/128, 1, 1), 256, SM128>>>(
        hcath, hcatl, 2*Dm, 0, Wlinh, Wlinl, nullptr, 2*Dm, 0, blin, 0,
        nullptr, nullptr,
        nullptr, hh, hl, HID, 0, HID, 2*Dm);

    // tab: [128,1000] + t-broadcast -> [1024,1000]
    gemm_mma<2,TOUTN,false,false,true,false><<<dim3((TBLV + 127)/128, 1, 1), 256, SM128>>>(
        hh, hl, HID, 0, nullptr, nullptr, Wtab, HID + 1, 0, btab, 0,
        nullptr, nullptr,
        out_tab, nullptr, nullptr, TBLV, 0, TBLV, HID);

    // idx: [128,100000] + t-broadcast -> [1024,100000]
    gemm_mma<2,TOUTN,false,false,true,false><<<dim3((IDXV + 127)/128, 1, 1), 256, SM128>>>(
        hh, hl, HID, 0, nullptr, nullptr, Widx, HID + 1, 0, bidx, 0,
        nullptr, nullptr,
        out_idx, nullptr, nullptr, IDXV, 0, IDXV, HID);
}

// round 11
// speedup vs baseline: 1.0439x; 1.0439x over previous
#include <cuda_runtime.h>
#include <cuda_bf16.h>
#include <math.h>
#include <stdint.h>

#define Bz    128
#define Sl    200
#define Dm    128
#define Hh    8
#define HD    16
#define Ll    2
#define DFF   2048
#define HID   512
#define TBLV  1000
#define IDXV  100000
#define TOUTN 8
#define NTOK  (Bz*Sl)   // 25600

// ================= scratch (device globals) =================
__device__ float g_x   [2*NTOK*Dm];
__device__ float g_qkv [2*NTOK*3*Dm];
__device__ __nv_bfloat16 g_hcath[Bz*2*Dm], g_hcatl[Bz*2*Dm];
__device__ __nv_bfloat16 g_hh[Bz*HID],     g_hl[Bz*HID];
__device__ __nv_bfloat16 g_xh [2*NTOK*Dm];
__device__ __nv_bfloat16 g_xl [2*NTOK*Dm];
__device__ __nv_bfloat16 g_ath[2*NTOK*Dm];
__device__ __nv_bfloat16 g_atl[2*NTOK*Dm];
__device__ __nv_bfloat16 g_ffh[(size_t)2*NTOK*DFF];
__device__ __nv_bfloat16 g_ffl[(size_t)2*NTOK*DFF];
__device__ __nv_bfloat16 g_Wqkvh[2*Ll*3*Dm*Dm], g_Wqkvl[2*Ll*3*Dm*Dm];
__device__ __nv_bfloat16 g_Woh  [2*Ll*Dm*Dm],   g_Wol  [2*Ll*Dm*Dm];
__device__ __nv_bfloat16 g_W1h  [2*Ll*DFF*Dm],  g_W1l  [2*Ll*DFF*Dm];
__device__ __nv_bfloat16 g_W2h  [2*Ll*Dm*DFF],  g_W2l  [2*Ll*Dm*DFF];
__device__ __nv_bfloat16 g_Wlinh[HID*2*Dm],     g_Wlinl[HID*2*Dm];

// ================= asm helpers (baseline PTX only) ==========
__device__ __forceinline__ uint32_t smem_u32(const void* p) {
    uint32_t a;
    asm("{ .reg .u64 t; cvta.to.shared.u64 t, %1; cvt.u32.u64 %0, t; }"
        : "=r"(a) : "l"(p));
    return a;
}
__device__ __forceinline__ void ldm_x4(uint32_t* r, uint32_t addr) {
    asm volatile("ldmatrix.sync.aligned.m8n8.x4.shared.b16 {%0,%1,%2,%3}, [%4];"
        : "=r"(r[0]), "=r"(r[1]), "=r"(r[2]), "=r"(r[3]) : "r"(addr));
}
__device__ __forceinline__ void mma16816(float* c, const uint32_t* a,
                                         uint32_t b0, uint32_t b1) {
    asm volatile("mma.sync.aligned.m16n8k16.row.col.f32.bf16.bf16.f32 "
        "{%0,%1,%2,%3}, {%4,%5,%6,%7}, {%8,%9}, {%0,%1,%2,%3};"
        : "+f"(c[0]), "+f"(c[1]), "+f"(c[2]), "+f"(c[3])
        : "r"(a[0]), "r"(a[1]), "r"(a[2]), "r"(a[3]), "r"(b0), "r"(b1));
}
#define CP16(dst, src) \
    asm volatile("cp.async.cg.shared.global [%0], [%1], 16;" :: "r"(dst), "l"(src))
#define CP_COMMIT() asm volatile("cp.async.commit_group;" ::: "memory")
#define CP_WAIT0()  asm volatile("cp.async.wait_group 0;" ::: "memory")

// ================= small utility kernels =================
__global__ void cvt_k(const float* __restrict__ in, __nv_bfloat16* __restrict__ h,
                      __nv_bfloat16* __restrict__ l, int n)
{
    int i = blockIdx.x * 256 + threadIdx.x;
    if (i < n) {
        float v = in[i];
        __nv_bfloat16 hi = __float2bfloat16(v);
        h[i] = hi;
        l[i] = __float2bfloat16(v - __bfloat162float(hi));
    }
}

__global__ void embed2_k(const int* __restrict__ ids0, const int* __restrict__ ids1,
                         const float* __restrict__ t0, const float* __restrict__ t1,
                         float* __restrict__ out,
                         __nv_bfloat16* __restrict__ oh, __nv_bfloat16* __restrict__ ol)
{
    int z = blockIdx.y, n = blockIdx.x, d = threadIdx.x;
    const int*   ids = z ? ids1 : ids0;
    const float* tab = z ? t1   : t0;
    size_t o = ((size_t)z*NTOK + n)*Dm + d;
    float v = tab[(size_t)ids[n]*Dm + d];
    out[o] = v;
    __nv_bfloat16 hi = __float2bfloat16(v);
    oh[o] = hi;
    ol[o] = __float2bfloat16(v - __bfloat162float(hi));
}

// ================= split-bf16 tensor-core GEMM ==============================
// C[M,N] = (Ah+Al)[M,K] @ (Bh+Bl)[N,K]^T + bias   (AlBl dropped)
// Block tile 128x128, stage BK=32, 8 warps (4x2), warp tile 32x64.
// 2-stage cp.async ring (80KB smem) -> 2 CTAs/SM.
// CVTB : B raw fp32 [N, ldb] (ldb=K+1); loader converts hi/lo on store.
// TOUT==8: time-broadcast epilogue, wlast = Bf[n*ldb + K].
// LNF  : requires N==128. x = LN(x + acc + bias); writes Cf=x, Ch/Cl=x hi/lo.
#define PITCH  80
#define TILEB  (128*PITCH)
#define STAGEB (4*TILEB)
#define GSMEM  (2*STAGEB)      // 81920

template<int TOUT, bool RELU, bool OUTBF16, bool CVTB, bool LNF>
__global__ __launch_bounds__(256, 2)
void gemm_mma(const __nv_bfloat16* __restrict__ Ah, const __nv_bfloat16* __restrict__ Al,
              int lda, size_t sA,
              const __nv_bfloat16* __restrict__ Bh16, const __nv_bfloat16* __restrict__ Bl16,
              const float* __restrict__ Bf,
              int ldb, size_t sB,
              const float* __restrict__ bias, size_t sBias,
              const float* __restrict__ gam, const float* __restrict__ bet,
              float* __restrict__ Cf,
              __nv_bfloat16* __restrict__ Ch, __nv_bfloat16* __restrict__ Cl,
              int ldc, size_t sC, int N, int K)
{
    extern __shared__ __align__(16) char sm[];

    int tid  = threadIdx.x;
    int wid  = tid >> 5;
    int lane = tid & 31;
    int z = blockIdx.z;
    Ah += (size_t)z * sA;  Al += (size_t)z * sA;
    if (!CVTB) { Bh16 += (size_t)z * sB; Bl16 += (size_t)z * sB; }
    bias += (size_t)z * sBias;
    if (LNF) { gam += (size_t)z * sBias; bet += (size_t)z * sBias; }
    if (LNF)         { Cf += (size_t)z * sC; Ch += (size_t)z * sC; Cl += (size_t)z * sC; }
    else if (OUTBF16){ Ch += (size_t)z * sC; Cl += (size_t)z * sC; }
    else             { Cf += (size_t)z * sC; }

    int m0 = blockIdx.y * 128;
    int n0 = blockIdx.x * 128;

    int lrow  = tid >> 1;
    int lhalf = tid & 1;
    int sdst = lrow*PITCH + lhalf*32;
    uint32_t sbase = smem_u32(sm);

    // compute mapping
    int wm = wid & 3;
    int wn = wid >> 2;
    int r8 = lane & 7, quad = lane >> 3;
    int arow = wm*32 + (quad & 1)*8 + r8;
    int aoff = (quad >> 1)*16;
    int brow = wn*64 + (quad >> 1)*8 + r8;
    int boff = (quad & 1)*16;

    float acc[2][8][4];
#pragma unroll
    for (int i = 0; i < 2; i++)
#pragma unroll
        for (int j = 0; j < 8; j++)
#pragma unroll
            for (int c = 0; c < 4; c++) acc[i][j][c] = 0.f;

    const int nst = K / 32;

    if (!CVTB) {
        const __nv_bfloat16* gAh = Ah + (size_t)(m0 + lrow)*lda + lhalf*16;
        const __nv_bfloat16* gAl = Al + (size_t)(m0 + lrow)*lda + lhalf*16;
        const __nv_bfloat16* gBh = Bh16 + (size_t)(n0 + lrow)*ldb + lhalf*16;
        const __nv_bfloat16* gBl = Bl16 + (size_t)(n0 + lrow)*ldb + lhalf*16;

#define ISSUE(s) do { \
        uint32_t st_ = sbase + ((s) & 1)*STAGEB + sdst; \
        int k0_ = (s)*32; \
        CP16(st_,              gAh + k0_); CP16(st_ + 16,             gAh + k0_ + 8); \
        CP16(st_ +   TILEB,    gAl + k0_); CP16(st_ +   TILEB + 16,   gAl + k0_ + 8); \
        CP16(st_ + 2*TILEB,    gBh + k0_); CP16(st_ + 2*TILEB + 16,   gBh + k0_ + 8); \
        CP16(st_ + 3*TILEB,    gBl + k0_); CP16(st_ + 3*TILEB + 16,   gBl + k0_ + 8); \
        CP_COMMIT(); } while (0)

        ISSUE(0);

        for (int it = 0; it < nst; ++it) {
            CP_WAIT0();
            __syncthreads();
            if (it + 1 < nst) ISSUE(it + 1);

            uint32_t stb = sbase + (it & 1)*STAGEB;
            uint32_t bAh = stb;
            uint32_t bAl = stb + TILEB;
            uint32_t bBh = stb + 2*TILEB;
            uint32_t bBl = stb + 3*TILEB;
#pragma unroll
            for (int ks = 0; ks < 2; ks++) {
                int ko = ks * 32;
                uint32_t ah[2][4], al[2][4];
#pragma unroll
                for (int mi = 0; mi < 2; mi++) {
                    ldm_x4(ah[mi], bAh + (arow + mi*16)*PITCH + ko + aoff);
                    ldm_x4(al[mi], bAl + (arow + mi*16)*PITCH + ko + aoff);
                }
#pragma unroll
                for (int pj = 0; pj < 4; pj++) {
                    uint32_t bh4[4], bl4[4];
                    ldm_x4(bh4, bBh + (brow + pj*16)*PITCH + ko + boff);
                    ldm_x4(bl4, bBl + (brow + pj*16)*PITCH + ko + boff);
#pragma unroll
                    for (int mi = 0; mi < 2; mi++) {
                        mma16816(acc[mi][2*pj],   ah[mi], bh4[0], bh4[1]);
                        mma16816(acc[mi][2*pj+1], ah[mi], bh4[2], bh4[3]);
                        mma16816(acc[mi][2*pj],   al[mi], bh4[0], bh4[1]);
                        mma16816(acc[mi][2*pj+1], al[mi], bh4[2], bh4[3]);
                        mma16816(acc[mi][2*pj],   ah[mi], bl4[0], bl4[1]);
                        mma16816(acc[mi][2*pj+1], ah[mi], bl4[2], bl4[3]);
                    }
                }
            }
        }
#undef ISSUE
    } else {
        int browg = min(n0 + lrow, N - 1);
        const __nv_bfloat16* gAh = Ah + (size_t)(m0 + lrow)*lda + lhalf*16;
        const __nv_bfloat16* gAl = Al + (size_t)(m0 + lrow)*lda + lhalf*16;
        const float* gB = Bf + (size_t)browg*ldb + lhalf*16;

        uint4 pa0, pa1, pa2, pa3;
        uint32_t pbh[8], pbl[8];

        auto loadstage = [&](int k0) {
            pa0 = *(const uint4*)(gAh + k0);
            pa1 = *(const uint4*)(gAh + k0 + 8);
            pa2 = *(const uint4*)(gAl + k0);
            pa3 = *(const uint4*)(gAl + k0 + 8);
#pragma unroll
            for (int j = 0; j < 8; j++) {
                float v0 = gB[k0 + 2*j];
                float v1 = gB[k0 + 2*j + 1];
                __nv_bfloat16 h0 = __float2bfloat16(v0);
                __nv_bfloat16 h1 = __float2bfloat16(v1);
                __nv_bfloat162 hp; hp.x = h0; hp.y = h1;
                __nv_bfloat162 lp;
                lp.x = __float2bfloat16(v0 - __bfloat162float(h0));
                lp.y = __float2bfloat16(v1 - __bfloat162float(h1));
                pbh[j] = *(uint32_t*)&hp;
                pbl[j] = *(uint32_t*)&lp;
            }
        };
        auto storestage = [&](int b) {
            char* stg = sm + b*STAGEB;
            *(uint4*)(stg + sdst)                = pa0;
            *(uint4*)(stg + sdst + 16)           = pa1;
            *(uint4*)(stg + TILEB + sdst)        = pa2;
            *(uint4*)(stg + TILEB + sdst + 16)   = pa3;
            *(uint4*)(stg + 2*TILEB + sdst)      = make_uint4(pbh[0],pbh[1],pbh[2],pbh[3]);
            *(uint4*)(stg + 2*TILEB + sdst + 16) = make_uint4(pbh[4],pbh[5],pbh[6],pbh[7]);
            *(uint4*)(stg + 3*TILEB + sdst)      = make_uint4(pbl[0],pbl[1],pbl[2],pbl[3]);
            *(uint4*)(stg + 3*TILEB + sdst + 16) = make_uint4(pbl[4],pbl[5],pbl[6],pbl[7]);
        };

        loadstage(0);
        storestage(0);

        for (int it = 0; it < nst; ++it) {
            int buf = it & 1;
            bool more = (it + 1) < nst;
            if (more) loadstage((it + 1) * 32);
            __syncthreads();

            uint32_t stb = sbase + buf*STAGEB;
            uint32_t bAh = stb;
            uint32_t bAl = stb + TILEB;
            uint32_t bBh = stb + 2*TILEB;
            uint32_t bBl = stb + 3*TILEB;
#pragma unroll
            for (int ks = 0; ks < 2; ks++) {
                int ko = ks * 32;
                uint32_t ah[2][4], al[2][4];
#pragma unroll
                for (int mi = 0; mi < 2; mi++) {
                    ldm_x4(ah[mi], bAh + (arow + mi*16)*PITCH + ko + aoff);
                    ldm_x4(al[mi], bAl + (arow + mi*16)*PITCH + ko + aoff);
                }
#pragma unroll
                for (int pj = 0; pj < 4; pj++) {
                    uint32_t bh4[4], bl4[4];
                    ldm_x4(bh4, bBh + (brow + pj*16)*PITCH + ko + boff);
                    ldm_x4(bl4, bBl + (brow + pj*16)*PITCH + ko + boff);
#pragma unroll
                    for (int mi = 0; mi < 2; mi++) {
                        mma16816(acc[mi][2*pj],   ah[mi], bh4[0], bh4[1]);
                        mma16816(acc[mi][2*pj+1], ah[mi], bh4[2], bh4[3]);
                        mma16816(acc[mi][2*pj],   al[mi], bh4[0], bh4[1]);
                        mma16816(acc[mi][2*pj+1], al[mi], bh4[2], bh4[3]);
                        mma16816(acc[mi][2*pj],   ah[mi], bl4[0], bl4[1]);
                        mma16816(acc[mi][2*pj+1], ah[mi], bl4[2], bl4[3]);
                    }
                }
            }

            if (more) {
                __syncthreads();
                storestage(buf ^ 1);
            }
        }
    }

    // ---- epilogue ----
    int mrow0 = m0 + wm*32 + (lane >> 2);
    int ncol0 = n0 + wn*64 + (lane & 3)*2;

    if (LNF) {
        __syncthreads();                 // stage smem now reusable
        float* red = (float*)sm;         // [128 rows][8 partials][2]
        int rbase = wm*32 + (lane >> 2);
        int pcol = wn*4 + (lane & 3);

#pragma unroll
        for (int mi = 0; mi < 2; mi++)
#pragma unroll
        for (int half = 0; half < 2; half++) {
            int row = rbase + mi*16 + half*8;
            int grow = m0 + row;
            float s = 0.f, s2 = 0.f;
#pragma unroll
            for (int nj = 0; nj < 8; nj++) {
                int col = (lane & 3)*2 + wn*64 + nj*8;
                float2 res = *(const float2*)(Cf + (size_t)grow*ldc + col);
                float t0 = acc[mi][nj][2*half]     + bias[col]     + res.x;
                float t1 = acc[mi][nj][2*half + 1] + bias[col + 1] + res.y;
                acc[mi][nj][2*half]     = t0;
                acc[mi][nj][2*half + 1] = t1;
                s  += t0 + t1;
                s2 += t0*t0 + t1*t1;
            }
            red[(row*8 + pcol)*2]     = s;
            red[(row*8 + pcol)*2 + 1] = s2;
        }
        __syncthreads();

#pragma unroll
        for (int mi = 0; mi < 2; mi++)
#pragma unroll
        for (int half = 0; half < 2; half++) {
            int row = rbase + mi*16 + half*8;
            int grow = m0 + row;
            float s = 0.f, s2 = 0.f;
#pragma unroll
            for (int p = 0; p < 8; p++) {
                s  += red[(row*8 + p)*2];
                s2 += red[(row*8 + p)*2 + 1];
            }
            float mean = s * (1.f/128.f);
            float var  = s2 * (1.f/128.f) - mean*mean;
            float inv  = rsqrtf(var + 1e-5f);
#pragma unroll
            for (int nj = 0; nj < 8; nj++) {
                int col = (lane & 3)*2 + wn*64 + nj*8;
                float t0 = acc[mi][nj][2*half];
                float t1 = acc[mi][nj][2*half + 1];
                float y0 = (t0 - mean)*inv*gam[col]     + bet[col];
                float y1 = (t1 - mean)*inv*gam[col + 1] + bet[col + 1];
                float2 yv; yv.x = y0; yv.y = y1;
                *(float2*)(Cf + (size_t)grow*ldc + col) = yv;
                __nv_bfloat16 h0 = __float2bfloat16(y0);
                __nv_bfloat16 h1 = __float2bfloat16(y1);
                __nv_bfloat162 hp; hp.x = h0; hp.y = h1;
                __nv_bfloat162 lp;
                lp.x = __float2bfloat16(y0 - __bfloat162float(h0));
                lp.y = __float2bfloat16(y1 - __bfloat162float(h1));
                *(__nv_bfloat162*)(Ch + (size_t)grow*ldc + col) = hp;
                *(__nv_bfloat162*)(Cl + (size_t)grow*ldc + col) = lp;
            }
        }
        return;
    }

#pragma unroll
    for (int mi = 0; mi < 2; mi++) {
#pragma unroll
        for (int nj = 0; nj < 8; nj++) {
            int col = ncol0 + nj*8;
            if (CVTB && col >= N) continue;
            float b0 = bias[col], b1 = bias[col + 1];
            float w0 = 0.f, w1 = 0.f;
            if (TOUT > 1) {
                w0 = Bf[(size_t)col*ldb + K];
                w1 = Bf[(size_t)(col + 1)*ldb + K];
            }
#pragma unroll
            for (int half = 0; half < 2; half++) {
                int row = mrow0 + mi*16 + half*8;
                float v0 = acc[mi][nj][2*half]     + b0;
                float v1 = acc[mi][nj][2*half + 1] + b1;
                if (RELU) { v0 = fmaxf(v0, 0.f); v1 = fmaxf(v1, 0.f); }
                if (TOUT > 1) {
#pragma unroll
                    for (int tt = 0; tt < TOUTN; tt++) {
                        float2 v; v.x = v0 + tt*w0; v.y = v1 + tt*w1;
                        *(float2*)(Cf + (size_t)(row*TOUTN + tt)*ldc + col) = v;
                    }
                } else if (OUTBF16) {
                    __nv_bfloat16 h0 = __float2bfloat16(v0);
                    __nv_bfloat16 h1 = __float2bfloat16(v1);
                    __nv_bfloat162 hp; hp.x = h0; hp.y = h1;
                    __nv_bfloat162 lp;
                    lp.x = __float2bfloat16(v0 - __bfloat162float(h0));
                    lp.y = __float2bfloat16(v1 - __bfloat162float(h1));
                    *(__nv_bfloat162*)(Ch + (size_t)row*ldc + col) = hp;
                    *(__nv_bfloat162*)(Cl + (size_t)row*ldc + col) = lp;
                } else {
                    float2 v; v.x = v0; v.y = v1;
                    *(float2*)(Cf + (size_t)row*ldc + col) = v;
                }
            }
        }
    }
}

// ================= attention: 2 j-segments per query, merged =================
__global__ __launch_bounds__(512)
void attn_k(const float* __restrict__ qkv,
            __nv_bfloat16* __restrict__ oh, __nv_bfloat16* __restrict__ ol)
{
    int z = blockIdx.y;
    int bh = blockIdx.x;
    int b = bh / Hh, h = bh % Hh;
    __shared__ float ks[Sl][HD];
    __shared__ float vs[Sl][HD];
    __shared__ float ms[Sl], ls[Sl];
    int tid = threadIdx.x;
    const float* base = qkv + ((size_t)z*NTOK + (size_t)b*Sl)*(3*Dm);

    for (int e = tid; e < Sl*HD; e += 512) {
        int s = e / HD, d = e % HD;
        ks[s][d] = base[s*(3*Dm) + Dm   + h*HD + d];
        vs[s][d] = base[s*(3*Dm) + 2*Dm + h*HD + d];
    }
    __syncthreads();

    int seg = (tid < Sl) ? 0 : 1;
    int s   = (tid < Sl) ? tid : tid - Sl;
    bool active = (tid < 2*Sl);

    float m = -1e30f, l = 0.f;
    float acc[HD];
#pragma unroll
    for (int d = 0; d < HD; d++) acc[d] = 0.f;

    if (active) {
        float q[HD];
#pragma unroll
        for (int d = 0; d < HD; d++)
            q[d] = base[s*(3*Dm) + h*HD + d] * 0.25f;   // 1/sqrt(16)

        int j0 = seg * (Sl/2);
        int j1 = j0 + (Sl/2);
        for (int j = j0; j < j1; j++) {
            float sc = 0.f;
#pragma unroll
            for (int d = 0; d < HD; d++) sc = fmaf(q[d], ks[j][d], sc);
            float nm  = fmaxf(m, sc);
            float cor = __expf(m - nm);
            float p   = __expf(sc - nm);
            l = l*cor + p;
#pragma unroll
            for (int d = 0; d < HD; d++) acc[d] = acc[d]*cor + p*vs[j][d];
            m = nm;
        }
    }
    __syncthreads();   // everyone done reading ks/vs

    if (active && seg == 1) {
        ms[s] = m; ls[s] = l;
#pragma unroll
        for (int d = 0; d < HD; d++) ks[s][d] = acc[d];
    }
    __syncthreads();

    if (active && seg == 0) {
        float m2 = ms[s], l2 = ls[s];
        float nm = fmaxf(m, m2);
        float c1 = __expf(m - nm);
        float c2 = __expf(m2 - nm);
        float L = l*c1 + l2*c2;
        float inv = 1.f / L;
        size_t o = ((size_t)z*NTOK + (size_t)b*Sl + s)*Dm + h*HD;
#pragma unroll
        for (int d = 0; d < HD; d++) {
            float v = (acc[d]*c1 + ks[s][d]*c2) * inv;
            __nv_bfloat16 hi = __float2bfloat16(v);
            oh[o + d] = hi;
            ol[o + d] = __float2bfloat16(v - __bfloat162float(hi));
        }
    }
}

// ---------------- sequence mean into split hcat --------------------------
__global__ void mean_k(const float* __restrict__ x,
                       __nv_bfloat16* __restrict__ oh, __nv_bfloat16* __restrict__ ol)
{
    int z = blockIdx.y;
    int b = blockIdx.x, d = threadIdx.x;
    const float* xp = x + ((size_t)z*NTOK + (size_t)b*Sl)*Dm;
    float s = 0.f;
    for (int j = 0; j < Sl; j++) s += xp[j*Dm + d];
    float v = s * (1.f/Sl);
    __nv_bfloat16 hi = __float2bfloat16(v);
    oh[b*(2*Dm) + z*Dm + d] = hi;
    ol[b*(2*Dm) + z*Dm + d] = __float2bfloat16(v - __bfloat162float(hi));
}

// ================= launcher =================
extern "C" void kernel_launch(void* const* d_in, const int* in_sizes, int n_in,
                              void* d_out, int out_size)
{
    const int*   tid_seq = (const int*)  d_in[0];
    const int*   iid_seq = (const int*)  d_in[1];
    const float* tab_emb = (const float*)d_in[2];
    const float* idx_emb = (const float*)d_in[3];
    const float* Wqkv = (const float*)d_in[4];
    const float* bqkv = (const float*)d_in[5];
    const float* Wo   = (const float*)d_in[6];
    const float* bo   = (const float*)d_in[7];
    const float* ln1g = (const float*)d_in[8];
    const float* ln1b = (const float*)d_in[9];
    const float* W1   = (const float*)d_in[10];
    const float* b1   = (const float*)d_in[11];
    const float* W2   = (const float*)d_in[12];
    const float* b2   = (const float*)d_in[13];
    const float* ln2g = (const float*)d_in[14];
    const float* ln2b = (const float*)d_in[15];
    const float* Wlin = (const float*)d_in[16];
    const float* blin = (const float*)d_in[17];
    const float* Wtab = (const float*)d_in[18];
    const float* btab = (const float*)d_in[19];
    const float* Widx = (const float*)d_in[20];
    const float* bidx = (const float*)d_in[21];

    float* out     = (float*)d_out;
    float* out_tab = out;
    float* out_idx = out + (size_t)Bz*TOUTN*TBLV;

    float *x, *qkv;
    __nv_bfloat16 *xh, *xl, *ath, *atl, *ffh, *ffl;
    __nv_bfloat16 *hcath, *hcatl, *hh, *hl;
    __nv_bfloat16 *Wqkvh, *Wqkvl, *Woh, *Wol, *W1h, *W1l, *W2h, *W2l;
    __nv_bfloat16 *Wlinh, *Wlinl;
    cudaGetSymbolAddress((void**)&x,    g_x);
    cudaGetSymbolAddress((void**)&qkv,  g_qkv);
    cudaGetSymbolAddress((void**)&xh,   g_xh);
    cudaGetSymbolAddress((void**)&xl,   g_xl);
    cudaGetSymbolAddress((void**)&ath,  g_ath);
    cudaGetSymbolAddress((void**)&atl,  g_atl);
    cudaGetSymbolAddress((void**)&ffh,  g_ffh);
    cudaGetSymbolAddress((void**)&ffl,  g_ffl);
    cudaGetSymbolAddress((void**)&hcath, g_hcath);
    cudaGetSymbolAddress((void**)&hcatl, g_hcatl);
    cudaGetSymbolAddress((void**)&hh,   g_hh);
    cudaGetSymbolAddress((void**)&hl,   g_hl);
    cudaGetSymbolAddress((void**)&Wqkvh, g_Wqkvh);
    cudaGetSymbolAddress((void**)&Wqkvl, g_Wqkvl);
    cudaGetSymbolAddress((void**)&Woh,   g_Woh);
    cudaGetSymbolAddress((void**)&Wol,   g_Wol);
    cudaGetSymbolAddress((void**)&W1h,   g_W1h);
    cudaGetSymbolAddress((void**)&W1l,   g_W1l);
    cudaGetSymbolAddress((void**)&W2h,   g_W2h);
    cudaGetSymbolAddress((void**)&W2l,   g_W2l);
    cudaGetSymbolAddress((void**)&Wlinh, g_Wlinh);
    cudaGetSymbolAddress((void**)&Wlinl, g_Wlinl);

    cudaFuncSetAttribute(gemm_mma<1,false,false,false,false>, cudaFuncAttributeMaxDynamicSharedMemorySize, GSMEM);
    cudaFuncSetAttribute(gemm_mma<1,false,false,false,true >, cudaFuncAttributeMaxDynamicSharedMemorySize, GSMEM);
    cudaFuncSetAttribute(gemm_mma<1,true, true, false,false>, cudaFuncAttributeMaxDynamicSharedMemorySize, GSMEM);
    cudaFuncSetAttribute(gemm_mma<TOUTN,false,false,true,false>, cudaFuncAttributeMaxDynamicSharedMemorySize, GSMEM);

    const int MT = NTOK / 128;  // 200
    const size_t sX   = (size_t)NTOK*Dm;
    const size_t sQKV = (size_t)NTOK*3*Dm;
    const size_t sFF  = (size_t)NTOK*DFF;

    cvt_k<<<(2*Ll*3*Dm*Dm + 255)/256, 256>>>(Wqkv, Wqkvh, Wqkvl, 2*Ll*3*Dm*Dm);
    cvt_k<<<(2*Ll*Dm*Dm   + 255)/256, 256>>>(Wo,   Woh,   Wol,   2*Ll*Dm*Dm);
    cvt_k<<<(2*Ll*DFF*Dm  + 255)/256, 256>>>(W1,   W1h,   W1l,   2*Ll*DFF*Dm);
    cvt_k<<<(2*Ll*Dm*DFF  + 255)/256, 256>>>(W2,   W2h,   W2l,   2*Ll*Dm*DFF);

    embed2_k<<<dim3(NTOK, 2), Dm>>>(tid_seq, iid_seq, tab_emb, idx_emb, x, xh, xl);

    for (int l = 0; l < Ll; l++) {
        // qkv = x @ Wqkv^T + b
        gemm_mma<1,false,false,false,false><<<dim3(3, MT, 2), 256, GSMEM>>>(
            xh, xl, Dm, sX,
            Wqkvh + (size_t)l*3*Dm*Dm, Wqkvl + (size_t)l*3*Dm*Dm, nullptr,
            Dm, (size_t)Ll*3*Dm*Dm,
            bqkv + (size_t)l*3*Dm, (size_t)Ll*3*Dm, nullptr, nullptr,
            qkv, nullptr, nullptr, 3*Dm, sQKV, 3*Dm, Dm);

        attn_k<<<dim3(Bz*Hh, 2), 512>>>(qkv, ath, atl);

        // x = LN(x + att @ Wo^T + bo)  -- fused epilogue
        gemm_mma<1,false,false,false,true><<<dim3(1, MT, 2), 256, GSMEM>>>(
            ath, atl, Dm, sX,
            Woh + (size_t)l*Dm*Dm, Wol + (size_t)l*Dm*Dm, nullptr,
            Dm, (size_t)Ll*Dm*Dm,
            bo + (size_t)l*Dm, (size_t)Ll*Dm,
            ln1g + (size_t)l*Dm, ln1b + (size_t)l*Dm,
            x, xh, xl, Dm, sX, Dm, Dm);

        // ff = relu(x @ W1^T + b1) -> bf16 hi/lo
        gemm_mma<1,true,true,false,false><<<dim3(DFF/128, MT, 2), 256, GSMEM>>>(
            xh, xl, Dm, sX,
            W1h + (size_t)l*DFF*Dm, W1l + (size_t)l*DFF*Dm, nullptr,
            Dm, (size_t)Ll*DFF*Dm,
            b1 + (size_t)l*DFF, (size_t)Ll*DFF, nullptr, nullptr,
            nullptr, ffh, ffl, DFF, sFF, DFF, Dm);

        // x = LN(x + ff @ W2^T + b2)  -- fused epilogue
        gemm_mma<1,false,false,false,true><<<dim3(1, MT, 2), 256, GSMEM>>>(
            ffh, ffl, DFF, sFF,
            W2h + (size_t)l*Dm*DFF, W2l + (size_t)l*Dm*DFF, nullptr,
            DFF, (size_t)Ll*Dm*DFF,
            b2 + (size_t)l*Dm, (size_t)Ll*Dm,
            ln2g + (size_t)l*Dm, ln2b + (size_t)l*Dm,
            x, xh, xl, Dm, sX, Dm, DFF);
    }

    mean_k<<<dim3(Bz, 2), Dm>>>(x, hcath, hcatl);

    cvt_k<<<(HID*2*Dm + 255)/256, 256>>>(Wlin, Wlinh, Wlinl, HID*2*Dm);

    // h = relu(hcat @ Wlin^T + blin) -> split   [128,512] K=256
    gemm_mma<1,true,true,false,false><<<dim3(HID/128, 1, 1), 256, GSMEM>>>(
        hcath, hcatl, 2*Dm, 0, Wlinh, Wlinl, nullptr, 2*Dm, 0, blin, 0,
        nullptr, nullptr,
        nullptr, hh, hl, HID, 0, HID, 2*Dm);

    // tab: [128,1000] + t-broadcast -> [1024,1000]
    gemm_mma<TOUTN,false,false,true,false><<<dim3((TBLV + 127)/128, 1, 1), 256, GSMEM>>>(
        hh, hl, HID, 0, nullptr, nullptr, Wtab, HID + 1, 0, btab, 0,
        nullptr, nullptr,
        out_tab, nullptr, nullptr, TBLV, 0, TBLV, HID);

    // idx: [128,100000] + t-broadcast -> [1024,100000]
    gemm_mma<TOUTN,false,false,true,false><<<dim3((IDXV + 127)/128, 1, 1), 256, GSMEM>>>(
        hh, hl, HID, 0, nullptr, nullptr, Widx, HID + 1, 0, bidx, 0,
        nullptr, nullptr,
        out_idx, nullptr, nullptr, IDXV, 0, IDXV, HID);
}

// round 12
// speedup vs baseline: 1.2468x; 1.1943x over previous
#include <cuda_runtime.h>
#include <cuda_fp16.h>
#include <math.h>
#include <stdint.h>

#define Bz    128
#define Sl    200
#define Dm    128
#define Hh    8
#define HD    16
#define Ll    2
#define DFF   2048
#define HID   512
#define TBLV  1000
#define IDXV  100000
#define TOUTN 8
#define NTOK  (Bz*Sl)   // 25600

// ================= scratch (device globals) =================
__device__ float g_x   [2*NTOK*Dm];
__device__ float g_qkv [2*NTOK*3*Dm];
__device__ __half g_hcath[Bz*2*Dm], g_hcatl[Bz*2*Dm];
__device__ __half g_hh[Bz*HID],     g_hl[Bz*HID];
__device__ __half g_xh [2*NTOK*Dm];
__device__ __half g_xl [2*NTOK*Dm];
__device__ __half g_ath[2*NTOK*Dm];
__device__ __half g_atl[2*NTOK*Dm];
__device__ __half g_ffh[(size_t)2*NTOK*DFF];
__device__ __half g_ffl[(size_t)2*NTOK*DFF];
__device__ __half g_Wqkvh[2*Ll*3*Dm*Dm];
__device__ __half g_Woh  [2*Ll*Dm*Dm];
__device__ __half g_W1h  [2*Ll*DFF*Dm];
__device__ __half g_W2h  [2*Ll*Dm*DFF];
__device__ __half g_Wlinh[HID*2*Dm];

// ================= asm helpers (baseline PTX only) ==========
__device__ __forceinline__ uint32_t smem_u32(const void* p) {
    uint32_t a;
    asm("{ .reg .u64 t; cvta.to.shared.u64 t, %1; cvt.u32.u64 %0, t; }"
        : "=r"(a) : "l"(p));
    return a;
}
__device__ __forceinline__ void ldm_x4(uint32_t* r, uint32_t addr) {
    asm volatile("ldmatrix.sync.aligned.m8n8.x4.shared.b16 {%0,%1,%2,%3}, [%4];"
        : "=r"(r[0]), "=r"(r[1]), "=r"(r[2]), "=r"(r[3]) : "r"(addr));
}
__device__ __forceinline__ void mma16816(float* c, const uint32_t* a,
                                         uint32_t b0, uint32_t b1) {
    asm volatile("mma.sync.aligned.m16n8k16.row.col.f32.f16.f16.f32 "
        "{%0,%1,%2,%3}, {%4,%5,%6,%7}, {%8,%9}, {%0,%1,%2,%3};"
        : "+f"(c[0]), "+f"(c[1]), "+f"(c[2]), "+f"(c[3])
        : "r"(a[0]), "r"(a[1]), "r"(a[2]), "r"(a[3]), "r"(b0), "r"(b1));
}
#define CP16(dst, src) \
    asm volatile("cp.async.cg.shared.global [%0], [%1], 16;" :: "r"(dst), "l"(src))
#define CP_COMMIT() asm volatile("cp.async.commit_group;" ::: "memory")
#define CP_WAIT0()  asm volatile("cp.async.wait_group 0;" ::: "memory")

__device__ __forceinline__ uint32_t pack_h2(float v0, float v1) {
    __half2 h = __halves2half2(__float2half_rn(v0), __float2half_rn(v1));
    return *(uint32_t*)&h;
}

// ================= small utility kernels =================
// weights: fp32 -> single fp16
__global__ void cvt_h(const float* __restrict__ in, __half* __restrict__ h, int n)
{
    int i = blockIdx.x * 256 + threadIdx.x;
    if (i < n) h[i] = __float2half_rn(in[i]);
}

__global__ void embed2_k(const int* __restrict__ ids0, const int* __restrict__ ids1,
                         const float* __restrict__ t0, const float* __restrict__ t1,
                         float* __restrict__ out,
                         __half* __restrict__ oh, __half* __restrict__ ol)
{
    int z = blockIdx.y, n = blockIdx.x, d = threadIdx.x;
    const int*   ids = z ? ids1 : ids0;
    const float* tab = z ? t1   : t0;
    size_t o = ((size_t)z*NTOK + n)*Dm + d;
    float v = tab[(size_t)ids[n]*Dm + d];
    out[o] = v;
    __half hi = __float2half_rn(v);
    oh[o] = hi;
    ol[o] = __float2half_rn(v - __half2float(hi));
}

// ================= split-fp16 tensor-core GEMM ==============================
// C[M,N] = (Ah+Al)[M,K] @ B[N,K]^T + bias.
// A: fp16 hi/lo split (22-bit effective).  B: single fp16.  2 MMA passes.
// Block tile 128x128, stage BK=32, 8 warps (4x2), warp tile 32x64.
// 2-stage cp.async ring, 3 tiles/stage (Ah, Al, B) = 60KB -> 2 CTAs/SM.
// CVTB : B raw fp32 [N, ldb] (ldb=K+1); loader converts to fp16 on store.
// TOUT==8: time-broadcast epilogue, wlast = Bf[n*ldb + K].
// LNF  : requires N==128. x = LN(x + acc + bias); writes Cf=x, Ch/Cl=x hi/lo.
#define PITCH  80
#define TILEB  (128*PITCH)
#define STAGEB (3*TILEB)
#define GSMEM  (2*STAGEB)      // 61440

template<int TOUT, bool RELU, bool OUTH, bool CVTB, bool LNF>
__global__ __launch_bounds__(256, 2)
void gemm_mma(const __half* __restrict__ Ah, const __half* __restrict__ Al,
              int lda, size_t sA,
              const __half* __restrict__ Bh16,
              const float* __restrict__ Bf,
              int ldb, size_t sB,
              const float* __restrict__ bias, size_t sBias,
              const float* __restrict__ gam, const float* __restrict__ bet,
              float* __restrict__ Cf,
              __half* __restrict__ Ch, __half* __restrict__ Cl,
              int ldc, size_t sC, int N, int K)
{
    extern __shared__ __align__(16) char sm[];

    int tid  = threadIdx.x;
    int wid  = tid >> 5;
    int lane = tid & 31;
    int z = blockIdx.z;
    Ah += (size_t)z * sA;  Al += (size_t)z * sA;
    if (!CVTB) Bh16 += (size_t)z * sB;
    bias += (size_t)z * sBias;
    if (LNF) { gam += (size_t)z * sBias; bet += (size_t)z * sBias; }
    if (LNF)      { Cf += (size_t)z * sC; Ch += (size_t)z * sC; Cl += (size_t)z * sC; }
    else if (OUTH){ Ch += (size_t)z * sC; Cl += (size_t)z * sC; }
    else          { Cf += (size_t)z * sC; }

    int m0 = blockIdx.y * 128;
    int n0 = blockIdx.x * 128;

    int lrow  = tid >> 1;
    int lhalf = tid & 1;
    int sdst = lrow*PITCH + lhalf*32;
    uint32_t sbase = smem_u32(sm);

    // compute mapping
    int wm = wid & 3;
    int wn = wid >> 2;
    int r8 = lane & 7, quad = lane >> 3;
    int arow = wm*32 + (quad & 1)*8 + r8;
    int aoff = (quad >> 1)*16;
    int brow = wn*64 + (quad >> 1)*8 + r8;
    int boff = (quad & 1)*16;

    float acc[2][8][4];
#pragma unroll
    for (int i = 0; i < 2; i++)
#pragma unroll
        for (int j = 0; j < 8; j++)
#pragma unroll
            for (int c = 0; c < 4; c++) acc[i][j][c] = 0.f;

    const int nst = K / 32;

    if (!CVTB) {
        const __half* gAh = Ah + (size_t)(m0 + lrow)*lda + lhalf*16;
        const __half* gAl = Al + (size_t)(m0 + lrow)*lda + lhalf*16;
        const __half* gB  = Bh16 + (size_t)(n0 + lrow)*ldb + lhalf*16;

#define ISSUE(s) do { \
        uint32_t st_ = sbase + ((s) & 1)*STAGEB + sdst; \
        int k0_ = (s)*32; \
        CP16(st_,            gAh + k0_); CP16(st_ + 16,           gAh + k0_ + 8); \
        CP16(st_ +   TILEB,  gAl + k0_); CP16(st_ +   TILEB + 16, gAl + k0_ + 8); \
        CP16(st_ + 2*TILEB,  gB  + k0_); CP16(st_ + 2*TILEB + 16, gB  + k0_ + 8); \
        CP_COMMIT(); } while (0)

        ISSUE(0);

        for (int it = 0; it < nst; ++it) {
            CP_WAIT0();
            __syncthreads();
            if (it + 1 < nst) ISSUE(it + 1);

            uint32_t stb = sbase + (it & 1)*STAGEB;
            uint32_t bAh = stb;
            uint32_t bAl = stb + TILEB;
            uint32_t bB  = stb + 2*TILEB;
#pragma unroll
            for (int ks = 0; ks < 2; ks++) {
                int ko = ks * 32;
                uint32_t ah[2][4], al[2][4];
#pragma unroll
                for (int mi = 0; mi < 2; mi++) {
                    ldm_x4(ah[mi], bAh + (arow + mi*16)*PITCH + ko + aoff);
                    ldm_x4(al[mi], bAl + (arow + mi*16)*PITCH + ko + aoff);
                }
#pragma unroll
                for (int pj = 0; pj < 4; pj++) {
                    uint32_t b4[4];
                    ldm_x4(b4, bB + (brow + pj*16)*PITCH + ko + boff);
#pragma unroll
                    for (int mi = 0; mi < 2; mi++) {
                        mma16816(acc[mi][2*pj],   ah[mi], b4[0], b4[1]);
                        mma16816(acc[mi][2*pj+1], ah[mi], b4[2], b4[3]);
                        mma16816(acc[mi][2*pj],   al[mi], b4[0], b4[1]);
                        mma16816(acc[mi][2*pj+1], al[mi], b4[2], b4[3]);
                    }
                }
            }
        }
#undef ISSUE
    } else {
        int browg = min(n0 + lrow, N - 1);
        const __half* gAh = Ah + (size_t)(m0 + lrow)*lda + lhalf*16;
        const __half* gAl = Al + (size_t)(m0 + lrow)*lda + lhalf*16;
        const float* gB = Bf + (size_t)browg*ldb + lhalf*16;

        uint4 pa0, pa1, pa2, pa3;
        uint32_t pb[8];

        auto loadstage = [&](int k0) {
            pa0 = *(const uint4*)(gAh + k0);
            pa1 = *(const uint4*)(gAh + k0 + 8);
            pa2 = *(const uint4*)(gAl + k0);
            pa3 = *(const uint4*)(gAl + k0 + 8);
#pragma unroll
            for (int j = 0; j < 8; j++)
                pb[j] = pack_h2(gB[k0 + 2*j], gB[k0 + 2*j + 1]);
        };
        auto storestage = [&](int b) {
            char* stg = sm + b*STAGEB;
            *(uint4*)(stg + sdst)                = pa0;
            *(uint4*)(stg + sdst + 16)           = pa1;
            *(uint4*)(stg + TILEB + sdst)        = pa2;
            *(uint4*)(stg + TILEB + sdst + 16)   = pa3;
            *(uint4*)(stg + 2*TILEB + sdst)      = make_uint4(pb[0],pb[1],pb[2],pb[3]);
            *(uint4*)(stg + 2*TILEB + sdst + 16) = make_uint4(pb[4],pb[5],pb[6],pb[7]);
        };

        loadstage(0);
        storestage(0);

        for (int it = 0; it < nst; ++it) {
            int buf = it & 1;
            bool more = (it + 1) < nst;
            if (more) loadstage((it + 1) * 32);
            __syncthreads();

            uint32_t stb = sbase + buf*STAGEB;
            uint32_t bAh = stb;
            uint32_t bAl = stb + TILEB;
            uint32_t bB  = stb + 2*TILEB;
#pragma unroll
            for (int ks = 0; ks < 2; ks++) {
                int ko = ks * 32;
                uint32_t ah[2][4], al[2][4];
#pragma unroll
                for (int mi = 0; mi < 2; mi++) {
                    ldm_x4(ah[mi], bAh + (arow + mi*16)*PITCH + ko + aoff);
                    ldm_x4(al[mi], bAl + (arow + mi*16)*PITCH + ko + aoff);
                }
#pragma unroll
                for (int pj = 0; pj < 4; pj++) {
                    uint32_t b4[4];
                    ldm_x4(b4, bB + (brow + pj*16)*PITCH + ko + boff);
#pragma unroll
                    for (int mi = 0; mi < 2; mi++) {
                        mma16816(acc[mi][2*pj],   ah[mi], b4[0], b4[1]);
                        mma16816(acc[mi][2*pj+1], ah[mi], b4[2], b4[3]);
                        mma16816(acc[mi][2*pj],   al[mi], b4[0], b4[1]);
                        mma16816(acc[mi][2*pj+1], al[mi], b4[2], b4[3]);
                    }
                }
            }

            if (more) {
                __syncthreads();
                storestage(buf ^ 1);
            }
        }
    }

    // ---- epilogue ----
    int mrow0 = m0 + wm*32 + (lane >> 2);
    int ncol0 = n0 + wn*64 + (lane & 3)*2;

    if (LNF) {
        __syncthreads();                 // stage smem now reusable
        float* red = (float*)sm;         // [128 rows][8 partials][2]
        int rbase = wm*32 + (lane >> 2);
        int pcol = wn*4 + (lane & 3);

#pragma unroll
        for (int mi = 0; mi < 2; mi++)
#pragma unroll
        for (int half = 0; half < 2; half++) {
            int row = rbase + mi*16 + half*8;
            int grow = m0 + row;
            float s = 0.f, s2 = 0.f;
#pragma unroll
            for (int nj = 0; nj < 8; nj++) {
                int col = (lane & 3)*2 + wn*64 + nj*8;
                float2 res = *(const float2*)(Cf + (size_t)grow*ldc + col);
                float t0 = acc[mi][nj][2*half]     + bias[col]     + res.x;
                float t1 = acc[mi][nj][2*half + 1] + bias[col + 1] + res.y;
                acc[mi][nj][2*half]     = t0;
                acc[mi][nj][2*half + 1] = t1;
                s  += t0 + t1;
                s2 += t0*t0 + t1*t1;
            }
            red[(row*8 + pcol)*2]     = s;
            red[(row*8 + pcol)*2 + 1] = s2;
        }
        __syncthreads();

#pragma unroll
        for (int mi = 0; mi < 2; mi++)
#pragma unroll
        for (int half = 0; half < 2; half++) {
            int row = rbase + mi*16 + half*8;
            int grow = m0 + row;
            float s = 0.f, s2 = 0.f;
#pragma unroll
            for (int p = 0; p < 8; p++) {
                s  += red[(row*8 + p)*2];
                s2 += red[(row*8 + p)*2 + 1];
            }
            float mean = s * (1.f/128.f);
            float var  = s2 * (1.f/128.f) - mean*mean;
            float inv  = rsqrtf(var + 1e-5f);
#pragma unroll
            for (int nj = 0; nj < 8; nj++) {
                int col = (lane & 3)*2 + wn*64 + nj*8;
                float t0 = acc[mi][nj][2*half];
                float t1 = acc[mi][nj][2*half + 1];
                float y0 = (t0 - mean)*inv*gam[col]     + bet[col];
                float y1 = (t1 - mean)*inv*gam[col + 1] + bet[col + 1];
                float2 yv; yv.x = y0; yv.y = y1;
                *(float2*)(Cf + (size_t)grow*ldc + col) = yv;
                __half h0 = __float2half_rn(y0);
                __half h1 = __float2half_rn(y1);
                __half2 hp = __halves2half2(h0, h1);
                __half2 lp = __halves2half2(
                    __float2half_rn(y0 - __half2float(h0)),
                    __float2half_rn(y1 - __half2float(h1)));
                *(__half2*)(Ch + (size_t)grow*ldc + col) = hp;
                *(__half2*)(Cl + (size_t)grow*ldc + col) = lp;
            }
        }
        return;
    }

#pragma unroll
    for (int mi = 0; mi < 2; mi++) {
#pragma unroll
        for (int nj = 0; nj < 8; nj++) {
            int col = ncol0 + nj*8;
            if (CVTB && col >= N) continue;
            float b0 = bias[col], b1 = bias[col + 1];
            float w0 = 0.f, w1 = 0.f;
            if (TOUT > 1) {
                w0 = Bf[(size_t)col*ldb + K];
                w1 = Bf[(size_t)(col + 1)*ldb + K];
            }
#pragma unroll
            for (int half = 0; half < 2; half++) {
                int row = mrow0 + mi*16 + half*8;
                float v0 = acc[mi][nj][2*half]     + b0;
                float v1 = acc[mi][nj][2*half + 1] + b1;
                if (RELU) { v0 = fmaxf(v0, 0.f); v1 = fmaxf(v1, 0.f); }
                if (TOUT > 1) {
#pragma unroll
                    for (int tt = 0; tt < TOUTN; tt++) {
                        float2 v; v.x = v0 + tt*w0; v.y = v1 + tt*w1;
                        *(float2*)(Cf + (size_t)(row*TOUTN + tt)*ldc + col) = v;
                    }
                } else if (OUTH) {
                    __half h0 = __float2half_rn(v0);
                    __half h1 = __float2half_rn(v1);
                    __half2 hp = __halves2half2(h0, h1);
                    __half2 lp = __halves2half2(
                        __float2half_rn(v0 - __half2float(h0)),
                        __float2half_rn(v1 - __half2float(h1)));
                    *(__half2*)(Ch + (size_t)row*ldc + col) = hp;
                    *(__half2*)(Cl + (size_t)row*ldc + col) = lp;
                } else {
                    float2 v; v.x = v0; v.y = v1;
                    *(float2*)(Cf + (size_t)row*ldc + col) = v;
                }
            }
        }
    }
}

// ================= attention (fp32 math, fp16-split output) =================
__global__ __launch_bounds__(256)
void attn_k(const float* __restrict__ qkv,
            __half* __restrict__ oh, __half* __restrict__ ol)
{
    int z = blockIdx.y;
    int bh = blockIdx.x;
    int b = bh / Hh, h = bh % Hh;
    __shared__ float ks[Sl][HD];
    __shared__ float vs[Sl][HD];
    int tid = threadIdx.x;
    const float* base = qkv + ((size_t)z*NTOK + (size_t)b*Sl)*(3*Dm);

    for (int e = tid; e < Sl*HD; e += 256) {
        int s = e / HD, d = e % HD;
        ks[s][d] = base[s*(3*Dm) + Dm   + h*HD + d];
        vs[s][d] = base[s*(3*Dm) + 2*Dm + h*HD + d];
    }
    __syncthreads();

    if (tid < Sl) {
        int s = tid;
        float q[HD];
#pragma unroll
        for (int d = 0; d < HD; d++)
            q[d] = base[s*(3*Dm) + h*HD + d] * 0.25f;   // 1/sqrt(16)

        float m = -1e30f, l = 0.f;
        float acc[HD];
#pragma unroll
        for (int d = 0; d < HD; d++) acc[d] = 0.f;

        for (int j = 0; j < Sl; j++) {
            float sc = 0.f;
#pragma unroll
            for (int d = 0; d < HD; d++) sc = fmaf(q[d], ks[j][d], sc);
            float nm  = fmaxf(m, sc);
            float cor = __expf(m - nm);
            float p   = __expf(sc - nm);
            l = l*cor + p;
#pragma unroll
            for (int d = 0; d < HD; d++) acc[d] = acc[d]*cor + p*vs[j][d];
            m = nm;
        }
        float inv = 1.f / l;
        size_t o = ((size_t)z*NTOK + (size_t)b*Sl + s)*Dm + h*HD;
#pragma unroll
        for (int d = 0; d < HD; d++) {
            float v = acc[d]*inv;
            __half hi = __float2half_rn(v);
            oh[o + d] = hi;
            ol[o + d] = __float2half_rn(v - __half2float(hi));
        }
    }
}

// ---------------- sequence mean into split hcat --------------------------
__global__ void mean_k(const float* __restrict__ x,
                       __half* __restrict__ oh, __half* __restrict__ ol)
{
    int z = blockIdx.y;
    int b = blockIdx.x, d = threadIdx.x;
    const float* xp = x + ((size_t)z*NTOK + (size_t)b*Sl)*Dm;
    float s = 0.f;
    for (int j = 0; j < Sl; j++) s += xp[j*Dm + d];
    float v = s * (1.f/Sl);
    __half hi = __float2half_rn(v);
    oh[b*(2*Dm) + z*Dm + d] = hi;
    ol[b*(2*Dm) + z*Dm + d] = __float2half_rn(v - __half2float(hi));
}

// ================= launcher =================
extern "C" void kernel_launch(void* const* d_in, const int* in_sizes, int n_in,
                              void* d_out, int out_size)
{
    const int*   tid_seq = (const int*)  d_in[0];
    const int*   iid_seq = (const int*)  d_in[1];
    const float* tab_emb = (const float*)d_in[2];
    const float* idx_emb = (const float*)d_in[3];
    const float* Wqkv = (const float*)d_in[4];
    const float* bqkv = (const float*)d_in[5];
    const float* Wo   = (const float*)d_in[6];
    const float* bo   = (const float*)d_in[7];
    const float* ln1g = (const float*)d_in[8];
    const float* ln1b = (const float*)d_in[9];
    const float* W1   = (const float*)d_in[10];
    const float* b1   = (const float*)d_in[11];
    const float* W2   = (const float*)d_in[12];
    const float* b2   = (const float*)d_in[13];
    const float* ln2g = (const float*)d_in[14];
    const float* ln2b = (const float*)d_in[15];
    const float* Wlin = (const float*)d_in[16];
    const float* blin = (const float*)d_in[17];
    const float* Wtab = (const float*)d_in[18];
    const float* btab = (const float*)d_in[19];
    const float* Widx = (const float*)d_in[20];
    const float* bidx = (const float*)d_in[21];

    float* out     = (float*)d_out;
    float* out_tab = out;
    float* out_idx = out + (size_t)Bz*TOUTN*TBLV;

    float *x, *qkv;
    __half *xh, *xl, *ath, *atl, *ffh, *ffl;
    __half *hcath, *hcatl, *hh, *hl;
    __half *Wqkvh, *Woh, *W1h, *W2h, *Wlinh;
    cudaGetSymbolAddress((void**)&x,    g_x);
    cudaGetSymbolAddress((void**)&qkv,  g_qkv);
    cudaGetSymbolAddress((void**)&xh,   g_xh);
    cudaGetSymbolAddress((void**)&xl,   g_xl);
    cudaGetSymbolAddress((void**)&ath,  g_ath);
    cudaGetSymbolAddress((void**)&atl,  g_atl);
    cudaGetSymbolAddress((void**)&ffh,  g_ffh);
    cudaGetSymbolAddress((void**)&ffl,  g_ffl);
    cudaGetSymbolAddress((void**)&hcath, g_hcath);
    cudaGetSymbolAddress((void**)&hcatl, g_hcatl);
    cudaGetSymbolAddress((void**)&hh,   g_hh);
    cudaGetSymbolAddress((void**)&hl,   g_hl);
    cudaGetSymbolAddress((void**)&Wqkvh, g_Wqkvh);
    cudaGetSymbolAddress((void**)&Woh,   g_Woh);
    cudaGetSymbolAddress((void**)&W1h,   g_W1h);
    cudaGetSymbolAddress((void**)&W2h,   g_W2h);
    cudaGetSymbolAddress((void**)&Wlinh, g_Wlinh);

    cudaFuncSetAttribute(gemm_mma<1,false,false,false,false>, cudaFuncAttributeMaxDynamicSharedMemorySize, GSMEM);
    cudaFuncSetAttribute(gemm_mma<1,false,false,false,true >, cudaFuncAttributeMaxDynamicSharedMemorySize, GSMEM);
    cudaFuncSetAttribute(gemm_mma<1,true, true, false,false>, cudaFuncAttributeMaxDynamicSharedMemorySize, GSMEM);
    cudaFuncSetAttribute(gemm_mma<TOUTN,false,false,true,false>, cudaFuncAttributeMaxDynamicSharedMemorySize, GSMEM);

    const int MT = NTOK / 128;  // 200
    const size_t sX   = (size_t)NTOK*Dm;
    const size_t sQKV = (size_t)NTOK*3*Dm;
    const size_t sFF  = (size_t)NTOK*DFF;

    cvt_h<<<(2*Ll*3*Dm*Dm + 255)/256, 256>>>(Wqkv, Wqkvh, 2*Ll*3*Dm*Dm);
    cvt_h<<<(2*Ll*Dm*Dm   + 255)/256, 256>>>(Wo,   Woh,   2*Ll*Dm*Dm);
    cvt_h<<<(2*Ll*DFF*Dm  + 255)/256, 256>>>(W1,   W1h,   2*Ll*DFF*Dm);
    cvt_h<<<(2*Ll*Dm*DFF  + 255)/256, 256>>>(W2,   W2h,   2*Ll*Dm*DFF);

    embed2_k<<<dim3(NTOK, 2), Dm>>>(tid_seq, iid_seq, tab_emb, idx_emb, x, xh, xl);

    for (int l = 0; l < Ll; l++) {
        // qkv = x @ Wqkv^T + b
        gemm_mma<1,false,false,false,false><<<dim3(3, MT, 2), 256, GSMEM>>>(
            xh, xl, Dm, sX,
            Wqkvh + (size_t)l*3*Dm*Dm, nullptr,
            Dm, (size_t)Ll*3*Dm*Dm,
            bqkv + (size_t)l*3*Dm, (size_t)Ll*3*Dm, nullptr, nullptr,
            qkv, nullptr, nullptr, 3*Dm, sQKV, 3*Dm, Dm);

        attn_k<<<dim3(Bz*Hh, 2), 256>>>(qkv, ath, atl);

        // x = LN(x + att @ Wo^T + bo)  -- fused epilogue
        gemm_mma<1,false,false,false,true><<<dim3(1, MT, 2), 256, GSMEM>>>(
            ath, atl, Dm, sX,
            Woh + (size_t)l*Dm*Dm, nullptr,
            Dm, (size_t)Ll*Dm*Dm,
            bo + (size_t)l*Dm, (size_t)Ll*Dm,
            ln1g + (size_t)l*Dm, ln1b + (size_t)l*Dm,
            x, xh, xl, Dm, sX, Dm, Dm);

        // ff = relu(x @ W1^T + b1) -> fp16 hi/lo
        gemm_mma<1,true,true,false,false><<<dim3(DFF/128, MT, 2), 256, GSMEM>>>(
            xh, xl, Dm, sX,
            W1h + (size_t)l*DFF*Dm, nullptr,
            Dm, (size_t)Ll*DFF*Dm,
            b1 + (size_t)l*DFF, (size_t)Ll*DFF, nullptr, nullptr,
            nullptr, ffh, ffl, DFF, sFF, DFF, Dm);

        // x = LN(x + ff @ W2^T + b2)  -- fused epilogue
        gemm_mma<1,false,false,false,true><<<dim3(1, MT, 2), 256, GSMEM>>>(
            ffh, ffl, DFF, sFF,
            W2h + (size_t)l*Dm*DFF, nullptr,
            DFF, (size_t)Ll*Dm*DFF,
            b2 + (size_t)l*Dm, (size_t)Ll*Dm,
            ln2g + (size_t)l*Dm, ln2b + (size_t)l*Dm,
            x, xh, xl, Dm, sX, Dm, DFF);
    }

    mean_k<<<dim3(Bz, 2), Dm>>>(x, hcath, hcatl);

    cvt_h<<<(HID*2*Dm + 255)/256, 256>>>(Wlin, Wlinh, HID*2*Dm);

    // h = relu(hcat @ Wlin^T + blin) -> split   [128,512] K=256
    gemm_mma<1,true,true,false,false><<<dim3(HID/128, 1, 1), 256, GSMEM>>>(
        hcath, hcatl, 2*Dm, 0, Wlinh, nullptr, 2*Dm, 0, blin, 0,
        nullptr, nullptr,
        nullptr, hh, hl, HID, 0, HID, 2*Dm);

    // tab: [128,1000] + t-broadcast -> [1024,1000]  (fp32 W -> fp16 in-kernel)
    gemm_mma<TOUTN,false,false,true,false><<<dim3((TBLV + 127)/128, 1, 1), 256, GSMEM>>>(
        hh, hl, HID, 0, nullptr, Wtab, HID + 1, 0, btab, 0,
        nullptr, nullptr,
        out_tab, nullptr, nullptr, TBLV, 0, TBLV, HID);

    // idx: [128,100000] + t-broadcast -> [1024,100000]
    gemm_mma<TOUTN,false,false,true,false><<<dim3((IDXV + 127)/128, 1, 1), 256, GSMEM>>>(
        hh, hl, HID, 0, nullptr, Widx, HID + 1, 0, bidx, 0,
        nullptr, nullptr,
        out_idx, nullptr, nullptr, IDXV, 0, IDXV, HID);
}

// round 13
// speedup vs baseline: 1.5902x; 1.2755x over previous
#include <cuda_runtime.h>
#include <cuda_fp16.h>
#include <math.h>
#include <stdint.h>

#define Bz    128
#define Sl    200
#define Dm    128
#define Hh    8
#define HD    16
#define Ll    2
#define DFF   2048
#define HID   512
#define TBLV  1000
#define IDXV  100000
#define TOUTN 8
#define NTOK  (Bz*Sl)   // 25600

// ================= scratch (device globals) =================
__device__ float g_x   [2*NTOK*Dm];
__device__ float g_qkv [2*NTOK*3*Dm];
__device__ __half g_hcath[Bz*2*Dm];
__device__ __half g_hh[Bz*HID];
__device__ __half g_xh [2*NTOK*Dm];
__device__ __half g_ath[2*NTOK*Dm];
__device__ __half g_ffh[(size_t)2*NTOK*DFF];
__device__ __half g_Wqkvh[2*Ll*3*Dm*Dm];
__device__ __half g_Woh  [2*Ll*Dm*Dm];
__device__ __half g_W1h  [2*Ll*DFF*Dm];
__device__ __half g_W2h  [2*Ll*Dm*DFF];
__device__ __half g_Wlinh[HID*2*Dm];

// ================= asm helpers (baseline PTX only) ==========
__device__ __forceinline__ uint32_t smem_u32(const void* p) {
    uint32_t a;
    asm("{ .reg .u64 t; cvta.to.shared.u64 t, %1; cvt.u32.u64 %0, t; }"
        : "=r"(a) : "l"(p));
    return a;
}
__device__ __forceinline__ void ldm_x4(uint32_t* r, uint32_t addr) {
    asm volatile("ldmatrix.sync.aligned.m8n8.x4.shared.b16 {%0,%1,%2,%3}, [%4];"
        : "=r"(r[0]), "=r"(r[1]), "=r"(r[2]), "=r"(r[3]) : "r"(addr));
}
__device__ __forceinline__ void mma16816(float* c, const uint32_t* a,
                                         uint32_t b0, uint32_t b1) {
    asm volatile("mma.sync.aligned.m16n8k16.row.col.f32.f16.f16.f32 "
        "{%0,%1,%2,%3}, {%4,%5,%6,%7}, {%8,%9}, {%0,%1,%2,%3};"
        : "+f"(c[0]), "+f"(c[1]), "+f"(c[2]), "+f"(c[3])
        : "r"(a[0]), "r"(a[1]), "r"(a[2]), "r"(a[3]), "r"(b0), "r"(b1));
}
#define CP16(dst, src) \
    asm volatile("cp.async.cg.shared.global [%0], [%1], 16;" :: "r"(dst), "l"(src))
#define CP_COMMIT() asm volatile("cp.async.commit_group;" ::: "memory")
#define CP_WAIT0()  asm volatile("cp.async.wait_group 0;" ::: "memory")

__device__ __forceinline__ uint32_t pack_h2(float v0, float v1) {
    __half2 h = __halves2half2(__float2half_rn(v0), __float2half_rn(v1));
    return *(uint32_t*)&h;
}

// ================= small utility kernels =================
__global__ void cvt_h(const float* __restrict__ in, __half* __restrict__ h, int n)
{
    int i = blockIdx.x * 256 + threadIdx.x;
    if (i < n) h[i] = __float2half_rn(in[i]);
}

__global__ void embed2_k(const int* __restrict__ ids0, const int* __restrict__ ids1,
                         const float* __restrict__ t0, const float* __restrict__ t1,
                         float* __restrict__ out, __half* __restrict__ oh)
{
    int z = blockIdx.y, n = blockIdx.x, d = threadIdx.x;
    const int*   ids = z ? ids1 : ids0;
    const float* tab = z ? t1   : t0;
    size_t o = ((size_t)z*NTOK + n)*Dm + d;
    float v = tab[(size_t)ids[n]*Dm + d];
    out[o] = v;
    oh[o] = __float2half_rn(v);
}

// ================= fp16 tensor-core GEMM ==============================
// C[M,N] = A[M,K] @ B[N,K]^T + bias.  A,B single fp16, 1 MMA pass.
// Block tile 128x128, stage BK=32, 8 warps (4x2), warp tile 32x64.
// 2-stage cp.async ring, 2 tiles/stage (A, B) = 40KB -> 2 CTAs/SM.
// CVTB : B raw fp32 [N, ldb] (ldb=K+1); loader converts to fp16 on store.
// TOUT==8: time-broadcast epilogue, wlast = Bf[n*ldb + K].
// LNF  : requires N==128. x = LN(x + acc + bias); writes Cf=x, Ch=x fp16.
#define PITCH  80
#define TILEB  (128*PITCH)
#define STAGEB (2*TILEB)
#define GSMEM  (2*STAGEB)      // 40960

template<int TOUT, bool RELU, bool OUTH, bool CVTB, bool LNF>
__global__ __launch_bounds__(256, 2)
void gemm_mma(const __half* __restrict__ A,
              int lda, size_t sA,
              const __half* __restrict__ Bh16,
              const float* __restrict__ Bf,
              int ldb, size_t sB,
              const float* __restrict__ bias, size_t sBias,
              const float* __restrict__ gam, const float* __restrict__ bet,
              float* __restrict__ Cf, __half* __restrict__ Ch,
              int ldc, size_t sC, int N, int K)
{
    extern __shared__ __align__(16) char sm[];

    int tid  = threadIdx.x;
    int wid  = tid >> 5;
    int lane = tid & 31;
    int z = blockIdx.z;
    A += (size_t)z * sA;
    if (!CVTB) Bh16 += (size_t)z * sB;
    bias += (size_t)z * sBias;
    if (LNF) { gam += (size_t)z * sBias; bet += (size_t)z * sBias; }
    if (LNF)      { Cf += (size_t)z * sC; Ch += (size_t)z * sC; }
    else if (OUTH)  Ch += (size_t)z * sC;
    else            Cf += (size_t)z * sC;

    int m0 = blockIdx.y * 128;
    int n0 = blockIdx.x * 128;

    int lrow  = tid >> 1;
    int lhalf = tid & 1;
    int sdst = lrow*PITCH + lhalf*32;
    uint32_t sbase = smem_u32(sm);

    // compute mapping
    int wm = wid & 3;
    int wn = wid >> 2;
    int r8 = lane & 7, quad = lane >> 3;
    int arow = wm*32 + (quad & 1)*8 + r8;
    int aoff = (quad >> 1)*16;
    int brow = wn*64 + (quad >> 1)*8 + r8;
    int boff = (quad & 1)*16;

    float acc[2][8][4];
#pragma unroll
    for (int i = 0; i < 2; i++)
#pragma unroll
        for (int j = 0; j < 8; j++)
#pragma unroll
            for (int c = 0; c < 4; c++) acc[i][j][c] = 0.f;

    const int nst = K / 32;

    if (!CVTB) {
        const __half* gA = A + (size_t)(m0 + lrow)*lda + lhalf*16;
        const __half* gB = Bh16 + (size_t)(n0 + lrow)*ldb + lhalf*16;

#define ISSUE(s) do { \
        uint32_t st_ = sbase + ((s) & 1)*STAGEB + sdst; \
        int k0_ = (s)*32; \
        CP16(st_,           gA + k0_); CP16(st_ + 16,          gA + k0_ + 8); \
        CP16(st_ + TILEB,   gB + k0_); CP16(st_ + TILEB + 16,  gB + k0_ + 8); \
        CP_COMMIT(); } while (0)

        ISSUE(0);

        for (int it = 0; it < nst; ++it) {
            CP_WAIT0();
            __syncthreads();
            if (it + 1 < nst) ISSUE(it + 1);

            uint32_t stb = sbase + (it & 1)*STAGEB;
            uint32_t bA = stb;
            uint32_t bB = stb + TILEB;
#pragma unroll
            for (int ks = 0; ks < 2; ks++) {
                int ko = ks * 32;
                uint32_t a4[2][4];
#pragma unroll
                for (int mi = 0; mi < 2; mi++)
                    ldm_x4(a4[mi], bA + (arow + mi*16)*PITCH + ko + aoff);
#pragma unroll
                for (int pj = 0; pj < 4; pj++) {
                    uint32_t b4[4];
                    ldm_x4(b4, bB + (brow + pj*16)*PITCH + ko + boff);
#pragma unroll
                    for (int mi = 0; mi < 2; mi++) {
                        mma16816(acc[mi][2*pj],   a4[mi], b4[0], b4[1]);
                        mma16816(acc[mi][2*pj+1], a4[mi], b4[2], b4[3]);
                    }
                }
            }
        }
#undef ISSUE
    } else {
        int browg = min(n0 + lrow, N - 1);
        const __half* gA = A + (size_t)(m0 + lrow)*lda + lhalf*16;
        const float* gB = Bf + (size_t)browg*ldb + lhalf*16;

        uint4 pa0, pa1;
        uint32_t pb[8];

        auto loadstage = [&](int k0) {
            pa0 = *(const uint4*)(gA + k0);
            pa1 = *(const uint4*)(gA + k0 + 8);
#pragma unroll
            for (int j = 0; j < 8; j++)
                pb[j] = pack_h2(gB[k0 + 2*j], gB[k0 + 2*j + 1]);
        };
        auto storestage = [&](int b) {
            char* stg = sm + b*STAGEB;
            *(uint4*)(stg + sdst)              = pa0;
            *(uint4*)(stg + sdst + 16)         = pa1;
            *(uint4*)(stg + TILEB + sdst)      = make_uint4(pb[0],pb[1],pb[2],pb[3]);
            *(uint4*)(stg + TILEB + sdst + 16) = make_uint4(pb[4],pb[5],pb[6],pb[7]);
        };

        loadstage(0);
        storestage(0);

        for (int it = 0; it < nst; ++it) {
            int buf = it & 1;
            bool more = (it + 1) < nst;
            if (more) loadstage((it + 1) * 32);
            __syncthreads();

            uint32_t stb = sbase + buf*STAGEB;
            uint32_t bA = stb;
            uint32_t bB = stb + TILEB;
#pragma unroll
            for (int ks = 0; ks < 2; ks++) {
                int ko = ks * 32;
                uint32_t a4[2][4];
#pragma unroll
                for (int mi = 0; mi < 2; mi++)
                    ldm_x4(a4[mi], bA + (arow + mi*16)*PITCH + ko + aoff);
#pragma unroll
                for (int pj = 0; pj < 4; pj++) {
                    uint32_t b4[4];
                    ldm_x4(b4, bB + (brow + pj*16)*PITCH + ko + boff);
#pragma unroll
                    for (int mi = 0; mi < 2; mi++) {
                        mma16816(acc[mi][2*pj],   a4[mi], b4[0], b4[1]);
                        mma16816(acc[mi][2*pj+1], a4[mi], b4[2], b4[3]);
                    }
                }
            }

            if (more) {
                __syncthreads();
                storestage(buf ^ 1);
            }
        }
    }

    // ---- epilogue ----
    int mrow0 = m0 + wm*32 + (lane >> 2);
    int ncol0 = n0 + wn*64 + (lane & 3)*2;

    if (LNF) {
        __syncthreads();                 // stage smem now reusable
        float* red = (float*)sm;         // [128 rows][8 partials][2]
        int rbase = wm*32 + (lane >> 2);
        int pcol = wn*4 + (lane & 3);

#pragma unroll
        for (int mi = 0; mi < 2; mi++)
#pragma unroll
        for (int half = 0; half < 2; half++) {
            int row = rbase + mi*16 + half*8;
            int grow = m0 + row;
            float s = 0.f, s2 = 0.f;
#pragma unroll
            for (int nj = 0; nj < 8; nj++) {
                int col = (lane & 3)*2 + wn*64 + nj*8;
                float2 res = *(const float2*)(Cf + (size_t)grow*ldc + col);
                float t0 = acc[mi][nj][2*half]     + bias[col]     + res.x;
                float t1 = acc[mi][nj][2*half + 1] + bias[col + 1] + res.y;
                acc[mi][nj][2*half]     = t0;
                acc[mi][nj][2*half + 1] = t1;
                s  += t0 + t1;
                s2 += t0*t0 + t1*t1;
            }
            red[(row*8 + pcol)*2]     = s;
            red[(row*8 + pcol)*2 + 1] = s2;
        }
        __syncthreads();

#pragma unroll
        for (int mi = 0; mi < 2; mi++)
#pragma unroll
        for (int half = 0; half < 2; half++) {
            int row = rbase + mi*16 + half*8;
            int grow = m0 + row;
            float s = 0.f, s2 = 0.f;
#pragma unroll
            for (int p = 0; p < 8; p++) {
                s  += red[(row*8 + p)*2];
                s2 += red[(row*8 + p)*2 + 1];
            }
            float mean = s * (1.f/128.f);
            float var  = s2 * (1.f/128.f) - mean*mean;
            float inv  = rsqrtf(var + 1e-5f);
#pragma unroll
            for (int nj = 0; nj < 8; nj++) {
                int col = (lane & 3)*2 + wn*64 + nj*8;
                float t0 = acc[mi][nj][2*half];
                float t1 = acc[mi][nj][2*half + 1];
                float y0 = (t0 - mean)*inv*gam[col]     + bet[col];
                float y1 = (t1 - mean)*inv*gam[col + 1] + bet[col + 1];
                float2 yv; yv.x = y0; yv.y = y1;
                *(float2*)(Cf + (size_t)grow*ldc + col) = yv;
                __half2 hp = __halves2half2(__float2half_rn(y0), __float2half_rn(y1));
                *(__half2*)(Ch + (size_t)grow*ldc + col) = hp;
            }
        }
        return;
    }

#pragma unroll
    for (int mi = 0; mi < 2; mi++) {
#pragma unroll
        for (int nj = 0; nj < 8; nj++) {
            int col = ncol0 + nj*8;
            if (CVTB && col >= N) continue;
            float b0 = bias[col], b1 = bias[col + 1];
            float w0 = 0.f, w1 = 0.f;
            if (TOUT > 1) {
                w0 = Bf[(size_t)col*ldb + K];
                w1 = Bf[(size_t)(col + 1)*ldb + K];
            }
#pragma unroll
            for (int half = 0; half < 2; half++) {
                int row = mrow0 + mi*16 + half*8;
                float v0 = acc[mi][nj][2*half]     + b0;
                float v1 = acc[mi][nj][2*half + 1] + b1;
                if (RELU) { v0 = fmaxf(v0, 0.f); v1 = fmaxf(v1, 0.f); }
                if (TOUT > 1) {
#pragma unroll
                    for (int tt = 0; tt < TOUTN; tt++) {
                        float2 v; v.x = v0 + tt*w0; v.y = v1 + tt*w1;
                        *(float2*)(Cf + (size_t)(row*TOUTN + tt)*ldc + col) = v;
                    }
                } else if (OUTH) {
                    __half2 hp = __halves2half2(__float2half_rn(v0), __float2half_rn(v1));
                    *(__half2*)(Ch + (size_t)row*ldc + col) = hp;
                } else {
                    float2 v; v.x = v0; v.y = v1;
                    *(float2*)(Cf + (size_t)row*ldc + col) = v;
                }
            }
        }
    }
}

// ================= attention (fp32 math, fp16 output) =================
__global__ __launch_bounds__(256)
void attn_k(const float* __restrict__ qkv, __half* __restrict__ oh)
{
    int z = blockIdx.y;
    int bh = blockIdx.x;
    int b = bh / Hh, h = bh % Hh;
    __shared__ float ks[Sl][HD];
    __shared__ float vs[Sl][HD];
    int tid = threadIdx.x;
    const float* base = qkv + ((size_t)z*NTOK + (size_t)b*Sl)*(3*Dm);

    for (int e = tid; e < Sl*HD; e += 256) {
        int s = e / HD, d = e % HD;
        ks[s][d] = base[s*(3*Dm) + Dm   + h*HD + d];
        vs[s][d] = base[s*(3*Dm) + 2*Dm + h*HD + d];
    }
    __syncthreads();

    if (tid < Sl) {
        int s = tid;
        float q[HD];
#pragma unroll
        for (int d = 0; d < HD; d++)
            q[d] = base[s*(3*Dm) + h*HD + d] * 0.25f;   // 1/sqrt(16)

        float m = -1e30f, l = 0.f;
        float acc[HD];
#pragma unroll
        for (int d = 0; d < HD; d++) acc[d] = 0.f;

        for (int j = 0; j < Sl; j++) {
            float sc = 0.f;
#pragma unroll
            for (int d = 0; d < HD; d++) sc = fmaf(q[d], ks[j][d], sc);
            float nm  = fmaxf(m, sc);
            float cor = __expf(m - nm);
            float p   = __expf(sc - nm);
            l = l*cor + p;
#pragma unroll
            for (int d = 0; d < HD; d++) acc[d] = acc[d]*cor + p*vs[j][d];
            m = nm;
        }
        float inv = 1.f / l;
        size_t o = ((size_t)z*NTOK + (size_t)b*Sl + s)*Dm + h*HD;
#pragma unroll
        for (int d = 0; d < HD; d++)
            oh[o + d] = __float2half_rn(acc[d]*inv);
    }
}

// ---------------- sequence mean into fp16 hcat --------------------------
__global__ void mean_k(const float* __restrict__ x, __half* __restrict__ oh)
{
    int z = blockIdx.y;
    int b = blockIdx.x, d = threadIdx.x;
    const float* xp = x + ((size_t)z*NTOK + (size_t)b*Sl)*Dm;
    float s = 0.f;
    for (int j = 0; j < Sl; j++) s += xp[j*Dm + d];
    oh[b*(2*Dm) + z*Dm + d] = __float2half_rn(s * (1.f/Sl));
}

// ================= launcher =================
extern "C" void kernel_launch(void* const* d_in, const int* in_sizes, int n_in,
                              void* d_out, int out_size)
{
    const int*   tid_seq = (const int*)  d_in[0];
    const int*   iid_seq = (const int*)  d_in[1];
    const float* tab_emb = (const float*)d_in[2];
    const float* idx_emb = (const float*)d_in[3];
    const float* Wqkv = (const float*)d_in[4];
    const float* bqkv = (const float*)d_in[5];
    const float* Wo   = (const float*)d_in[6];
    const float* bo   = (const float*)d_in[7];
    const float* ln1g = (const float*)d_in[8];
    const float* ln1b = (const float*)d_in[9];
    const float* W1   = (const float*)d_in[10];
    const float* b1   = (const float*)d_in[11];
    const float* W2   = (const float*)d_in[12];
    const float* b2   = (const float*)d_in[13];
    const float* ln2g = (const float*)d_in[14];
    const float* ln2b = (const float*)d_in[15];
    const float* Wlin = (const float*)d_in[16];
    const float* blin = (const float*)d_in[17];
    const float* Wtab = (const float*)d_in[18];
    const float* btab = (const float*)d_in[19];
    const float* Widx = (const float*)d_in[20];
    const float* bidx = (const float*)d_in[21];

    float* out     = (float*)d_out;
    float* out_tab = out;
    float* out_idx = out + (size_t)Bz*TOUTN*TBLV;

    float *x, *qkv;
    __half *xh, *ath, *ffh, *hcath, *hh;
    __half *Wqkvh, *Woh, *W1h, *W2h, *Wlinh;
    cudaGetSymbolAddress((void**)&x,    g_x);
    cudaGetSymbolAddress((void**)&qkv,  g_qkv);
    cudaGetSymbolAddress((void**)&xh,   g_xh);
    cudaGetSymbolAddress((void**)&ath,  g_ath);
    cudaGetSymbolAddress((void**)&ffh,  g_ffh);
    cudaGetSymbolAddress((void**)&hcath, g_hcath);
    cudaGetSymbolAddress((void**)&hh,   g_hh);
    cudaGetSymbolAddress((void**)&Wqkvh, g_Wqkvh);
    cudaGetSymbolAddress((void**)&Woh,   g_Woh);
    cudaGetSymbolAddress((void**)&W1h,   g_W1h);
    cudaGetSymbolAddress((void**)&W2h,   g_W2h);
    cudaGetSymbolAddress((void**)&Wlinh, g_Wlinh);

    cudaFuncSetAttribute(gemm_mma<1,false,false,false,false>, cudaFuncAttributeMaxDynamicSharedMemorySize, GSMEM);
    cudaFuncSetAttribute(gemm_mma<1,false,false,false,true >, cudaFuncAttributeMaxDynamicSharedMemorySize, GSMEM);
    cudaFuncSetAttribute(gemm_mma<1,true, true, false,false>, cudaFuncAttributeMaxDynamicSharedMemorySize, GSMEM);
    cudaFuncSetAttribute(gemm_mma<TOUTN,false,false,true,false>, cudaFuncAttributeMaxDynamicSharedMemorySize, GSMEM);

    const int MT = NTOK / 128;  // 200
    const size_t sX   = (size_t)NTOK*Dm;
    const size_t sQKV = (size_t)NTOK*3*Dm;
    const size_t sFF  = (size_t)NTOK*DFF;

    cvt_h<<<(2*Ll*3*Dm*Dm + 255)/256, 256>>>(Wqkv, Wqkvh, 2*Ll*3*Dm*Dm);
    cvt_h<<<(2*Ll*Dm*Dm   + 255)/256, 256>>>(Wo,   Woh,   2*Ll*Dm*Dm);
    cvt_h<<<(2*Ll*DFF*Dm  + 255)/256, 256>>>(W1,   W1h,   2*Ll*DFF*Dm);
    cvt_h<<<(2*Ll*Dm*DFF  + 255)/256, 256>>>(W2,   W2h,   2*Ll*Dm*DFF);

    embed2_k<<<dim3(NTOK, 2), Dm>>>(tid_seq, iid_seq, tab_emb, idx_emb, x, xh);

    for (int l = 0; l < Ll; l++) {
        // qkv = x @ Wqkv^T + b
        gemm_mma<1,false,false,false,false><<<dim3(3, MT, 2), 256, GSMEM>>>(
            xh, Dm, sX,
            Wqkvh + (size_t)l*3*Dm*Dm, nullptr,
            Dm, (size_t)Ll*3*Dm*Dm,
            bqkv + (size_t)l*3*Dm, (size_t)Ll*3*Dm, nullptr, nullptr,
            qkv, nullptr, 3*Dm, sQKV, 3*Dm, Dm);

        attn_k<<<dim3(Bz*Hh, 2), 256>>>(qkv, ath);

        // x = LN(x + att @ Wo^T + bo)  -- fused epilogue
        gemm_mma<1,false,false,false,true><<<dim3(1, MT, 2), 256, GSMEM>>>(
            ath, Dm, sX,
            Woh + (size_t)l*Dm*Dm, nullptr,
            Dm, (size_t)Ll*Dm*Dm,
            bo + (size_t)l*Dm, (size_t)Ll*Dm,
            ln1g + (size_t)l*Dm, ln1b + (size_t)l*Dm,
            x, xh, Dm, sX, Dm, Dm);

        // ff = relu(x @ W1^T + b1) -> fp16
        gemm_mma<1,true,true,false,false><<<dim3(DFF/128, MT, 2), 256, GSMEM>>>(
            xh, Dm, sX,
            W1h + (size_t)l*DFF*Dm, nullptr,
            Dm, (size_t)Ll*DFF*Dm,
            b1 + (size_t)l*DFF, (size_t)Ll*DFF, nullptr, nullptr,
            nullptr, ffh, DFF, sFF, DFF, Dm);

        // x = LN(x + ff @ W2^T + b2)  -- fused epilogue
        gemm_mma<1,false,false,false,true><<<dim3(1, MT, 2), 256, GSMEM>>>(
            ffh, DFF, sFF,
            W2h + (size_t)l*Dm*DFF, nullptr,
            DFF, (size_t)Ll*Dm*DFF,
            b2 + (size_t)l*Dm, (size_t)Ll*Dm,
            ln2g + (size_t)l*Dm, ln2b + (size_t)l*Dm,
            x, xh, Dm, sX, Dm, DFF);
    }

    mean_k<<<dim3(Bz, 2), Dm>>>(x, hcath);

    cvt_h<<<(HID*2*Dm + 255)/256, 256>>>(Wlin, Wlinh, HID*2*Dm);

    // h = relu(hcat @ Wlin^T + blin) -> fp16   [128,512] K=256
    gemm_mma<1,true,true,false,false><<<dim3(HID/128, 1, 1), 256, GSMEM>>>(
        hcath, 2*Dm, 0, Wlinh, nullptr, 2*Dm, 0, blin, 0,
        nullptr, nullptr,
        nullptr, hh, HID, 0, HID, 2*Dm);

    // tab: [128,1000] + t-broadcast -> [1024,1000]  (fp32 W -> fp16 in-kernel)
    gemm_mma<TOUTN,false,false,true,false><<<dim3((TBLV + 127)/128, 1, 1), 256, GSMEM>>>(
        hh, HID, 0, nullptr, Wtab, HID + 1, 0, btab, 0,
        nullptr, nullptr,
        out_tab, nullptr, TBLV, 0, TBLV, HID);

    // idx: [128,100000] + t-broadcast -> [1024,100000]
    gemm_mma<TOUTN,false,false,true,false><<<dim3((IDXV + 127)/128, 1, 1), 256, GSMEM>>>(
        hh, HID, 0, nullptr, Widx, HID + 1, 0, bidx, 0,
        nullptr, nullptr,
        out_idx, nullptr, IDXV, 0, IDXV, HID);
}